// round 2
// baseline (speedup 1.0000x reference)
#include <cuda_runtime.h>
#include <math.h>

// Problem constants
#define BB   2
#define SS   2048
#define DIM  1024
#define HH   16
#define QD   64
#define VD   96
#define NF   32          // QD/2
#define HV   (HH*VD)     // 1536
#define NROW (BB*SS)     // 4096

// ---------------------------------------------------------------------------
// Scratch (device globals; no allocation allowed)
// ---------------------------------------------------------------------------
__device__ float g_xn [NROW*DIM];     // normalized x
__device__ float g_q  [NROW*HH*QD];   // q (post-rope), layout (b,s,h,d)
__device__ float g_k  [NROW*QD];      // k (post-rope)
__device__ float g_v  [NROW*VD];      // v
__device__ float g_ctx[NROW*HV];      // attention output, layout (b,s,h,vd)
__device__ float g_sin[SS*NF];
__device__ float g_cos[SS*NF];

// ---------------------------------------------------------------------------
// RoPE tables: freq[i] = 2048^(-i/31); theta = s * freq
// ---------------------------------------------------------------------------
__global__ void rope_table_kernel() {
    int s = blockIdx.x, i = threadIdx.x;
    double freq = exp(-((double)i / 31.0) * log(2048.0));
    double th = (double)s * freq;
    double si, co;
    sincos(th, &si, &co);
    g_sin[s*NF + i] = (float)si;
    g_cos[s*NF + i] = (float)co;
}

// ---------------------------------------------------------------------------
// RMSNorm: one block per row (1024 elems, 256 threads, float4 each)
// ---------------------------------------------------------------------------
__global__ void rmsnorm_kernel(const float* __restrict__ x,
                               const float* __restrict__ w) {
    int row = blockIdx.x;
    int t = threadIdx.x;
    const float4* xr = (const float4*)(x + (size_t)row * DIM);
    float4 xv = xr[t];
    float ss = xv.x*xv.x + xv.y*xv.y + xv.z*xv.z + xv.w*xv.w;
    #pragma unroll
    for (int o = 16; o; o >>= 1) ss += __shfl_xor_sync(0xffffffffu, ss, o);
    __shared__ float wsum[8];
    if ((t & 31) == 0) wsum[t >> 5] = ss;
    __syncthreads();
    float tot = 0.f;
    #pragma unroll
    for (int i = 0; i < 8; i++) tot += wsum[i];
    float scale = rsqrtf(tot * (1.0f / DIM) + 1e-8f);
    const float4* wr = (const float4*)w;
    float4 wv = wr[t];
    float4 o;
    o.x = xv.x * wv.x * scale;
    o.y = xv.y * wv.y * scale;
    o.z = xv.z * wv.z * scale;
    o.w = xv.w * wv.w * scale;
    ((float4*)(g_xn + (size_t)row * DIM))[t] = o;
}

// ---------------------------------------------------------------------------
// Tiled SGEMM: C[M,N] = A[M,K] @ B[K,N] (+ bias[n])
// 64x64 tile, BK=16, 256 threads, 4x4 per thread. M%64==0, K%16==0; N guarded.
// ---------------------------------------------------------------------------
__global__ void sgemm64(const float* __restrict__ A, const float* __restrict__ Bm,
                        const float* __restrict__ bias, float* __restrict__ C,
                        int M, int N, int K) {
    __shared__ float As[16][64];
    __shared__ float Bs[16][68];
    int t = threadIdx.x;
    int m0 = blockIdx.y * 64, n0 = blockIdx.x * 64;
    int tx = t & 15, ty = t >> 4;
    float acc[4][4] = {};
    for (int k0 = 0; k0 < K; k0 += 16) {
        #pragma unroll
        for (int i = 0; i < 4; i++) {
            int l = t * 4 + i;
            int mm = l >> 4, kk = l & 15;          // A tile 64(m) x 16(k)
            As[kk][mm] = A[(size_t)(m0 + mm) * K + k0 + kk];
            int kb = l >> 6, nb = l & 63;          // B tile 16(k) x 64(n)
            int n = n0 + nb;
            Bs[kb][nb] = (n < N) ? Bm[(size_t)(k0 + kb) * N + n] : 0.f;
        }
        __syncthreads();
        #pragma unroll
        for (int kk = 0; kk < 16; kk++) {
            float4 a = *(const float4*)&As[kk][ty * 4];
            float4 b = *(const float4*)&Bs[kk][tx * 4];
            float av[4] = {a.x, a.y, a.z, a.w};
            float bv[4] = {b.x, b.y, b.z, b.w};
            #pragma unroll
            for (int r = 0; r < 4; r++)
                #pragma unroll
                for (int c = 0; c < 4; c++)
                    acc[r][c] += av[r] * bv[c];
        }
        __syncthreads();
    }
    #pragma unroll
    for (int r = 0; r < 4; r++) {
        int m = m0 + ty * 4 + r;
        #pragma unroll
        for (int c = 0; c < 4; c++) {
            int n = n0 + tx * 4 + c;
            if (n < N) {
                float v = acc[r][c];
                if (bias) v += bias[n];
                C[(size_t)m * N + n] = v;
            }
        }
    }
}

// ---------------------------------------------------------------------------
// RoPE (split-concat form): out[i] = x[2i]*cos - x[2i+1]*sin ; out[nf+i] = x[2i]*sin + x[2i+1]*cos
// ---------------------------------------------------------------------------
__global__ void rope_q_kernel() {
    int bs = blockIdx.x;              // b*S + s
    int s = bs & (SS - 1);
    int h = threadIdx.x >> 5, i = threadIdx.x & 31;
    float* base = g_q + (size_t)bs * (HH * QD) + h * QD;
    float x1 = base[2 * i], x2 = base[2 * i + 1];
    float sn = g_sin[s * NF + i], cs = g_cos[s * NF + i];
    __syncwarp();
    base[i]      = x1 * cs - x2 * sn;
    base[32 + i] = x1 * sn + x2 * cs;
}

__global__ void rope_k_kernel() {
    int bs = blockIdx.x;
    int s = bs & (SS - 1);
    int i = threadIdx.x;
    float* base = g_k + (size_t)bs * QD;
    float x1 = base[2 * i], x2 = base[2 * i + 1];
    float sn = g_sin[s * NF + i], cs = g_cos[s * NF + i];
    __syncwarp();
    base[i]      = x1 * cs - x2 * sn;
    base[32 + i] = x1 * sn + x2 * cs;
}

// ---------------------------------------------------------------------------
// Flash attention with softcap. Since logits = 5*tanh(.) in [-5,5], no running
// max is needed: accumulate exp(s) and exp(s)*v directly, divide at the end.
// Block: 256 threads, 64 query rows, one (b,h). 4 threads per row (quad).
// ---------------------------------------------------------------------------
struct FlashSmem {
    float q[64][68];
    float k[64][68];
    float p[64][68];
    float v[64][96];
};
#define FLASH_SMEM_BYTES ((int)sizeof(FlashSmem))

__global__ void flash_kernel(const float* __restrict__ bias) {
    extern __shared__ unsigned char smraw[];
    FlashSmem& sm = *(FlashSmem*)smraw;
    int t = threadIdx.x;
    int b = blockIdx.z, h = blockIdx.y, i0 = blockIdx.x * 64;

    // load Q tile (64 x 64)
    for (int idx = t; idx < 64 * 64; idx += 256) {
        int r = idx >> 6, d = idx & 63;
        sm.q[r][d] = g_q[((size_t)(b * SS + i0 + r) * HH + h) * QD + d];
    }

    int r = t >> 2, ql = t & 3;
    float acc[24] = {};
    float lsumTot = 0.f;
    const float* brow = bias + (((size_t)b * HH + h) * SS + (i0 + r)) * SS;

    for (int j0 = 0; j0 < SS; j0 += 64) {
        __syncthreads();   // prior PV done before overwriting k/v
        for (int idx = t; idx < 64 * 64; idx += 256) {
            int rr = idx >> 6, d = idx & 63;
            sm.k[rr][d] = g_k[(size_t)(b * SS + j0 + rr) * QD + d];
        }
        for (int idx = t; idx < 64 * 96; idx += 256) {
            int rr = idx / 96, c = idx - rr * 96;
            sm.v[rr][c] = g_v[(size_t)(b * SS + j0 + rr) * VD + c];
        }
        __syncthreads();

        // scores: each thread does 16 j's (jj = ql + 4u), full 64-d dot
        float sc[16];
        #pragma unroll
        for (int u = 0; u < 16; u++) sc[u] = brow[j0 + ql + 4 * u];
        #pragma unroll 4
        for (int d4 = 0; d4 < 16; d4++) {
            float4 qv = *(const float4*)&sm.q[r][4 * d4];
            #pragma unroll
            for (int u = 0; u < 16; u++) {
                float4 kv = *(const float4*)&sm.k[ql + 4 * u][4 * d4];
                sc[u] += qv.x * kv.x + qv.y * kv.y + qv.z * kv.z + qv.w * kv.w;
            }
        }
        float lsum = 0.f;
        #pragma unroll
        for (int u = 0; u < 16; u++) {
            float s = 5.0f * tanhf(sc[u] * 0.2f);
            float p = expf(s);
            sm.p[r][ql + 4 * u] = p;
            lsum += p;
        }
        lsum += __shfl_xor_sync(0xffffffffu, lsum, 1);
        lsum += __shfl_xor_sync(0xffffffffu, lsum, 2);
        lsumTot += lsum;
        __syncwarp();   // p written by this quad, read below

        // PV: each thread owns 24 v-columns (co..co+23) of its row
        int co = ql * 24;
        #pragma unroll 4
        for (int jj = 0; jj < 64; jj++) {
            float pv = sm.p[r][jj];
            const float4* vrow = (const float4*)&sm.v[jj][co];
            #pragma unroll
            for (int i6 = 0; i6 < 6; i6++) {
                float4 v4 = vrow[i6];
                acc[i6 * 4 + 0] += pv * v4.x;
                acc[i6 * 4 + 1] += pv * v4.y;
                acc[i6 * 4 + 2] += pv * v4.z;
                acc[i6 * 4 + 3] += pv * v4.w;
            }
        }
    }

    float inv = 1.0f / lsumTot;
    float* orow = g_ctx + ((size_t)(b * SS + i0 + r) * HH + h) * VD + ql * 24;
    #pragma unroll
    for (int i = 0; i < 24; i++) orow[i] = acc[i] * inv;
}

// ---------------------------------------------------------------------------
// Launch
// ---------------------------------------------------------------------------
extern "C" void kernel_launch(void* const* d_in, const int* in_sizes, int n_in,
                              void* d_out, int out_size) {
    const float* x    = (const float*)d_in[0];
    const float* bias = (const float*)d_in[1];
    const float* rmsw = (const float*)d_in[2];
    const float* Wq   = (const float*)d_in[3];
    const float* Wk   = (const float*)d_in[4];
    const float* Wv   = (const float*)d_in[5];
    const float* bv   = (const float*)d_in[6];
    const float* Wo   = (const float*)d_in[7];
    const float* bo   = (const float*)d_in[8];
    float* out = (float*)d_out;

    void *p_xn, *p_q, *p_k, *p_v, *p_ctx;
    cudaGetSymbolAddress(&p_xn,  g_xn);
    cudaGetSymbolAddress(&p_q,   g_q);
    cudaGetSymbolAddress(&p_k,   g_k);
    cudaGetSymbolAddress(&p_v,   g_v);
    cudaGetSymbolAddress(&p_ctx, g_ctx);
    float* xn  = (float*)p_xn;
    float* q   = (float*)p_q;
    float* k   = (float*)p_k;
    float* v   = (float*)p_v;
    float* ctx = (float*)p_ctx;

    cudaFuncSetAttribute(flash_kernel,
                         cudaFuncAttributeMaxDynamicSharedMemorySize,
                         FLASH_SMEM_BYTES);

    rope_table_kernel<<<SS, NF>>>();
    rmsnorm_kernel<<<NROW, 256>>>(x, rmsw);

    // projections
    sgemm64<<<dim3(HH * QD / 64, NROW / 64), 256>>>(xn, Wq, nullptr, q, NROW, HH * QD, DIM);
    sgemm64<<<dim3(1,            NROW / 64), 256>>>(xn, Wk, nullptr, k, NROW, QD, DIM);
    sgemm64<<<dim3(2,            NROW / 64), 256>>>(xn, Wv, bv,      v, NROW, VD, DIM);

    rope_q_kernel<<<NROW, 512>>>();
    rope_k_kernel<<<NROW, 32>>>();

    // attention
    flash_kernel<<<dim3(SS / 64, HH, BB), 256, FLASH_SMEM_BYTES>>>(bias);

    // output projection
    sgemm64<<<dim3(DIM / 64, NROW / 64), 256>>>(ctx, Wo, bo, out, NROW, DIM, HV);
}

// round 3
// speedup vs baseline: 1.5814x; 1.5814x over previous
#include <cuda_runtime.h>
#include <cuda_bf16.h>
#include <math.h>
#include <stdint.h>

// Problem constants
#define BB   2
#define SS   2048
#define DIM  1024
#define HH   16
#define QD   64
#define VD   96
#define NF   32          // QD/2
#define HV   (HH*VD)     // 1536
#define NROW (BB*SS)     // 4096

// ---------------------------------------------------------------------------
// Scratch (device globals; no allocation allowed)
// ---------------------------------------------------------------------------
__device__ float g_xn [NROW*DIM];     // normalized x
__device__ float g_q  [NROW*HH*QD];   // q (post-rope), layout (b,s,h,d)
__device__ float g_k  [NROW*QD];      // k (post-rope)
__device__ float g_v  [NROW*VD];      // v
__device__ float g_ctx[NROW*HV];      // attention output, layout (b,s,h,vd)
__device__ float g_sin[SS*NF];
__device__ float g_cos[SS*NF];

// ---------------------------------------------------------------------------
// RoPE tables: freq[i] = 2048^(-i/31); theta = s * freq
// ---------------------------------------------------------------------------
__global__ void rope_table_kernel() {
    int s = blockIdx.x, i = threadIdx.x;
    double freq = exp(-((double)i / 31.0) * log(2048.0));
    double th = (double)s * freq;
    double si, co;
    sincos(th, &si, &co);
    g_sin[s*NF + i] = (float)si;
    g_cos[s*NF + i] = (float)co;
}

// ---------------------------------------------------------------------------
// RMSNorm: one block per row (1024 elems, 256 threads, float4 each)
// ---------------------------------------------------------------------------
__global__ void rmsnorm_kernel(const float* __restrict__ x,
                               const float* __restrict__ w) {
    int row = blockIdx.x;
    int t = threadIdx.x;
    const float4* xr = (const float4*)(x + (size_t)row * DIM);
    float4 xv = xr[t];
    float ss = xv.x*xv.x + xv.y*xv.y + xv.z*xv.z + xv.w*xv.w;
    #pragma unroll
    for (int o = 16; o; o >>= 1) ss += __shfl_xor_sync(0xffffffffu, ss, o);
    __shared__ float wsum[8];
    if ((t & 31) == 0) wsum[t >> 5] = ss;
    __syncthreads();
    float tot = 0.f;
    #pragma unroll
    for (int i = 0; i < 8; i++) tot += wsum[i];
    float scale = rsqrtf(tot * (1.0f / DIM) + 1e-8f);
    const float4* wr = (const float4*)w;
    float4 wv = wr[t];
    float4 o;
    o.x = xv.x * wv.x * scale;
    o.y = xv.y * wv.y * scale;
    o.z = xv.z * wv.z * scale;
    o.w = xv.w * wv.w * scale;
    ((float4*)(g_xn + (size_t)row * DIM))[t] = o;
}

// ---------------------------------------------------------------------------
// Tiled SGEMM: C[M,N] = A[M,K] @ B[K,N] (+ bias[n])
// ---------------------------------------------------------------------------
__global__ void sgemm64(const float* __restrict__ A, const float* __restrict__ Bm,
                        const float* __restrict__ bias, float* __restrict__ C,
                        int M, int N, int K) {
    __shared__ float As[16][64];
    __shared__ float Bs[16][68];
    int t = threadIdx.x;
    int m0 = blockIdx.y * 64, n0 = blockIdx.x * 64;
    int tx = t & 15, ty = t >> 4;
    float acc[4][4] = {};
    for (int k0 = 0; k0 < K; k0 += 16) {
        #pragma unroll
        for (int i = 0; i < 4; i++) {
            int l = t * 4 + i;
            int mm = l >> 4, kk = l & 15;
            As[kk][mm] = A[(size_t)(m0 + mm) * K + k0 + kk];
            int kb = l >> 6, nb = l & 63;
            int n = n0 + nb;
            Bs[kb][nb] = (n < N) ? Bm[(size_t)(k0 + kb) * N + n] : 0.f;
        }
        __syncthreads();
        #pragma unroll
        for (int kk = 0; kk < 16; kk++) {
            float4 a = *(const float4*)&As[kk][ty * 4];
            float4 b = *(const float4*)&Bs[kk][tx * 4];
            float av[4] = {a.x, a.y, a.z, a.w};
            float bv[4] = {b.x, b.y, b.z, b.w};
            #pragma unroll
            for (int r = 0; r < 4; r++)
                #pragma unroll
                for (int c = 0; c < 4; c++)
                    acc[r][c] += av[r] * bv[c];
        }
        __syncthreads();
    }
    #pragma unroll
    for (int r = 0; r < 4; r++) {
        int m = m0 + ty * 4 + r;
        #pragma unroll
        for (int c = 0; c < 4; c++) {
            int n = n0 + tx * 4 + c;
            if (n < N) {
                float v = acc[r][c];
                if (bias) v += bias[n];
                C[(size_t)m * N + n] = v;
            }
        }
    }
}

// ---------------------------------------------------------------------------
// RoPE
// ---------------------------------------------------------------------------
__global__ void rope_q_kernel() {
    int bs = blockIdx.x;
    int s = bs & (SS - 1);
    int h = threadIdx.x >> 5, i = threadIdx.x & 31;
    float* base = g_q + (size_t)bs * (HH * QD) + h * QD;
    float x1 = base[2 * i], x2 = base[2 * i + 1];
    float sn = g_sin[s * NF + i], cs = g_cos[s * NF + i];
    __syncwarp();
    base[i]      = x1 * cs - x2 * sn;
    base[32 + i] = x1 * sn + x2 * cs;
}

__global__ void rope_k_kernel() {
    int bs = blockIdx.x;
    int s = bs & (SS - 1);
    int i = threadIdx.x;
    float* base = g_k + (size_t)bs * QD;
    float x1 = base[2 * i], x2 = base[2 * i + 1];
    float sn = g_sin[s * NF + i], cs = g_cos[s * NF + i];
    __syncwarp();
    base[i]      = x1 * cs - x2 * sn;
    base[32 + i] = x1 * sn + x2 * cs;
}

// ---------------------------------------------------------------------------
// Fast math helpers: pure-FFMA exp2 and reciprocal (no MUFU; B300 MUFU is
// only 0.5 op/cyc/SM, which would serialize 134M softcap evaluations).
// ---------------------------------------------------------------------------
__device__ __forceinline__ float fexp2(float x) {
    // valid for |x| <= ~40, rel err ~1e-7
    float y = x + 12582912.0f;                 // 1.5*2^23: round to int
    float f = x - (y - 12582912.0f);           // frac in [-0.5, 0.5]
    int   k = __float_as_int(y) - 0x4B400000;  // integer part
    float p =              1.5404e-4f;
    p = fmaf(p, f, 1.3333558e-3f);
    p = fmaf(p, f, 9.6181291e-3f);
    p = fmaf(p, f, 5.5504109e-2f);
    p = fmaf(p, f, 2.4022651e-1f);
    p = fmaf(p, f, 6.9314718e-1f);
    p = fmaf(p, f, 1.0f);
    float sc = __int_as_float((k + 127) << 23);
    return p * sc;
}

__device__ __forceinline__ float frcp(float w) {
    // w > 0; bit-hack guess + 3 Newton iters -> ~fp32 accuracy, no MUFU
    float r = __int_as_float(0x7EF311C3 - __float_as_int(w));
    r = r * fmaf(-w, r, 2.0f);
    r = r * fmaf(-w, r, 2.0f);
    r = r * fmaf(-w, r, 2.0f);
    return r;
}

// p = exp(5*tanh(s/5)), entirely on the FMA pipe.
__device__ __forceinline__ float softcap_exp(float s) {
    // 2u*log2(e) with u = s/5 -> 0.57707802*s ; clamp for exp2 safety
    float x1 = fminf(fmaxf(s * 0.57707802f, -30.f), 30.f);
    float e2 = fexp2(x1);                    // e^{2u}
    float r  = frcp(1.0f + e2);
    // t = 5 - 10*r ; p = exp2(t*log2 e) = exp2(7.2134752 - 14.4269504*r)
    return fexp2(fmaf(-14.4269504f, r, 7.2134752f));
}

// ---------------------------------------------------------------------------
// Tensor-core flash attention (bf16 split-precision mma.sync).
// Block: 256 threads (8 warps), 128 query rows, one (b,h). j-tiles of 64.
// Every fp32 operand is split x = hi + lo (bf16); products use 3 MMAs
// (hi*hi + hi*lo + lo*hi) => ~2^-16 relative error, fp32-like.
// ---------------------------------------------------------------------------
#define QSTR 72   // smem row stride in bf16 elems (64 + 8 pad -> conflict-free)
#define FLASH_SMEM ((128 + 64 + 96) * QSTR * 2 * 2)  // hi+lo, 2B each = 82944

__device__ __forceinline__ void mma_bf16(float* c, const uint32_t* a,
                                         uint32_t b0, uint32_t b1) {
    asm volatile(
        "mma.sync.aligned.m16n8k16.row.col.f32.bf16.bf16.f32 "
        "{%0,%1,%2,%3}, {%4,%5,%6,%7}, {%8,%9}, {%0,%1,%2,%3};\n"
        : "+f"(c[0]), "+f"(c[1]), "+f"(c[2]), "+f"(c[3])
        : "r"(a[0]), "r"(a[1]), "r"(a[2]), "r"(a[3]), "r"(b0), "r"(b1));
}

__device__ __forceinline__ void split_store(__nv_bfloat16* hi, __nv_bfloat16* lo,
                                            int idx, float x) {
    __nv_bfloat16 h = __float2bfloat16(x);
    hi[idx] = h;
    lo[idx] = __float2bfloat16(x - __bfloat162float(h));
}

__device__ __forceinline__ uint32_t pack_hi2(float a, float b) {
    __nv_bfloat162 t;
    t.x = __float2bfloat16(a);
    t.y = __float2bfloat16(b);
    return *reinterpret_cast<uint32_t*>(&t);
}
__device__ __forceinline__ uint32_t pack_lo2(float a, float b) {
    __nv_bfloat16 ha = __float2bfloat16(a);
    __nv_bfloat16 hb = __float2bfloat16(b);
    __nv_bfloat162 t;
    t.x = __float2bfloat16(a - __bfloat162float(ha));
    t.y = __float2bfloat16(b - __bfloat162float(hb));
    return *reinterpret_cast<uint32_t*>(&t);
}

__global__ __launch_bounds__(256, 1) void flash_mma_kernel(const float* __restrict__ bias) {
    extern __shared__ __nv_bfloat16 smraw[];
    __nv_bfloat16* qh = smraw;
    __nv_bfloat16* ql = qh + 128 * QSTR;
    __nv_bfloat16* kh = ql + 128 * QSTR;
    __nv_bfloat16* kl = kh + 64 * QSTR;
    __nv_bfloat16* vh = kl + 64 * QSTR;     // V transposed: [vd][j]
    __nv_bfloat16* vl = vh + 96 * QSTR;

    int t = threadIdx.x, w = t >> 5, l = t & 31;
    int b = blockIdx.z, h = blockIdx.y, i0 = blockIdx.x * 128;
    int gid = l >> 2, lc = l & 3;
    int m0 = w * 16;

    // load+split Q tile (128 x 64)
    for (int idx = t; idx < 128 * 64; idx += 256) {
        int r = idx >> 6, d = idx & 63;
        float x = g_q[((size_t)(b * SS + i0 + r) * HH + h) * QD + d];
        split_store(qh, ql, r * QSTR + d, x);
    }

    float o[12][4] = {};
    float lsum0 = 0.f, lsum1 = 0.f;
    const float* bb = bias + ((size_t)(b * HH + h) * SS + (i0 + m0 + gid)) * SS;

    for (int j0 = 0; j0 < SS; j0 += 64) {
        __syncthreads();   // previous tile's smem reads done
        for (int idx = t; idx < 64 * 64; idx += 256) {
            int r = idx >> 6, d = idx & 63;
            float x = g_k[(size_t)(b * SS + j0 + r) * QD + d];
            split_store(kh, kl, r * QSTR + d, x);
        }
        for (int idx = t; idx < 64 * 96; idx += 256) {
            int r = idx / 96, c = idx - r * 96;
            float x = g_v[(size_t)(b * SS + j0 + r) * VD + c];
            split_store(vh, vl, c * QSTR + r, x);   // transposed
        }
        __syncthreads();

        // ---- S = Q K^T + bias (init C frags with bias) ----
        float sc[8][4];
        #pragma unroll
        for (int nf = 0; nf < 8; nf++) {
            const float* bp = bb + j0 + nf * 8 + lc * 2;
            float2 b01 = *(const float2*)bp;
            float2 b23 = *(const float2*)(bp + (size_t)8 * SS);
            sc[nf][0] = b01.x; sc[nf][1] = b01.y;
            sc[nf][2] = b23.x; sc[nf][3] = b23.y;
        }
        #pragma unroll
        for (int kk = 0; kk < 4; kk++) {
            int d0 = kk * 16 + lc * 2;
            uint32_t ah[4], al[4];
            ah[0] = *(const uint32_t*)&qh[(m0 + gid) * QSTR + d0];
            ah[1] = *(const uint32_t*)&qh[(m0 + gid + 8) * QSTR + d0];
            ah[2] = *(const uint32_t*)&qh[(m0 + gid) * QSTR + d0 + 8];
            ah[3] = *(const uint32_t*)&qh[(m0 + gid + 8) * QSTR + d0 + 8];
            al[0] = *(const uint32_t*)&ql[(m0 + gid) * QSTR + d0];
            al[1] = *(const uint32_t*)&ql[(m0 + gid + 8) * QSTR + d0];
            al[2] = *(const uint32_t*)&ql[(m0 + gid) * QSTR + d0 + 8];
            al[3] = *(const uint32_t*)&ql[(m0 + gid + 8) * QSTR + d0 + 8];
            #pragma unroll
            for (int nf = 0; nf < 8; nf++) {
                int n = nf * 8 + gid;
                uint32_t bh0 = *(const uint32_t*)&kh[n * QSTR + kk * 16 + lc * 2];
                uint32_t bh1 = *(const uint32_t*)&kh[n * QSTR + kk * 16 + lc * 2 + 8];
                uint32_t bl0 = *(const uint32_t*)&kl[n * QSTR + kk * 16 + lc * 2];
                uint32_t bl1 = *(const uint32_t*)&kl[n * QSTR + kk * 16 + lc * 2 + 8];
                mma_bf16(sc[nf], ah, bh0, bh1);
                mma_bf16(sc[nf], ah, bl0, bl1);
                mma_bf16(sc[nf], al, bh0, bh1);
            }
        }

        // ---- softcap + exp (FMA pipe only) + row sums ----
        #pragma unroll
        for (int nf = 0; nf < 8; nf++) {
            #pragma unroll
            for (int e = 0; e < 4; e++)
                sc[nf][e] = softcap_exp(sc[nf][e]);
            lsum0 += sc[nf][0] + sc[nf][1];
            lsum1 += sc[nf][2] + sc[nf][3];
        }

        // ---- repack P (C layout -> A layout, hi/lo split) ----
        uint32_t ph[4][4], pl[4][4];
        #pragma unroll
        for (int kj = 0; kj < 4; kj++) {
            ph[kj][0] = pack_hi2(sc[2*kj][0],   sc[2*kj][1]);
            ph[kj][1] = pack_hi2(sc[2*kj][2],   sc[2*kj][3]);
            ph[kj][2] = pack_hi2(sc[2*kj+1][0], sc[2*kj+1][1]);
            ph[kj][3] = pack_hi2(sc[2*kj+1][2], sc[2*kj+1][3]);
            pl[kj][0] = pack_lo2(sc[2*kj][0],   sc[2*kj][1]);
            pl[kj][1] = pack_lo2(sc[2*kj][2],   sc[2*kj][3]);
            pl[kj][2] = pack_lo2(sc[2*kj+1][0], sc[2*kj+1][1]);
            pl[kj][3] = pack_lo2(sc[2*kj+1][2], sc[2*kj+1][3]);
        }

        // ---- O += P V ----
        #pragma unroll
        for (int nf = 0; nf < 12; nf++) {
            int n = nf * 8 + gid;
            #pragma unroll
            for (int kj = 0; kj < 4; kj++) {
                uint32_t bh0 = *(const uint32_t*)&vh[n * QSTR + kj * 16 + lc * 2];
                uint32_t bh1 = *(const uint32_t*)&vh[n * QSTR + kj * 16 + lc * 2 + 8];
                uint32_t bl0 = *(const uint32_t*)&vl[n * QSTR + kj * 16 + lc * 2];
                uint32_t bl1 = *(const uint32_t*)&vl[n * QSTR + kj * 16 + lc * 2 + 8];
                mma_bf16(o[nf], ph[kj], bh0, bh1);
                mma_bf16(o[nf], ph[kj], bl0, bl1);
                mma_bf16(o[nf], pl[kj], bh0, bh1);
            }
        }
    }

    // quad-reduce row sums (lanes within quad share the row)
    lsum0 += __shfl_xor_sync(0xffffffffu, lsum0, 1);
    lsum0 += __shfl_xor_sync(0xffffffffu, lsum0, 2);
    lsum1 += __shfl_xor_sync(0xffffffffu, lsum1, 1);
    lsum1 += __shfl_xor_sync(0xffffffffu, lsum1, 2);
    float inv0 = frcp(lsum0), inv1 = frcp(lsum1);

    int row0 = b * SS + i0 + m0 + gid;
    #pragma unroll
    for (int nf = 0; nf < 12; nf++) {
        int vd = nf * 8 + lc * 2;
        float* p0 = g_ctx + ((size_t)row0 * HH + h) * VD + vd;
        p0[0] = o[nf][0] * inv0;
        p0[1] = o[nf][1] * inv0;
        float* p1 = p0 + (size_t)8 * HH * VD;
        p1[0] = o[nf][2] * inv1;
        p1[1] = o[nf][3] * inv1;
    }
}

// ---------------------------------------------------------------------------
// Launch
// ---------------------------------------------------------------------------
extern "C" void kernel_launch(void* const* d_in, const int* in_sizes, int n_in,
                              void* d_out, int out_size) {
    const float* x    = (const float*)d_in[0];
    const float* bias = (const float*)d_in[1];
    const float* rmsw = (const float*)d_in[2];
    const float* Wq   = (const float*)d_in[3];
    const float* Wk   = (const float*)d_in[4];
    const float* Wv   = (const float*)d_in[5];
    const float* bv   = (const float*)d_in[6];
    const float* Wo   = (const float*)d_in[7];
    const float* bo   = (const float*)d_in[8];
    float* out = (float*)d_out;

    void *p_xn, *p_q, *p_k, *p_v, *p_ctx;
    cudaGetSymbolAddress(&p_xn,  g_xn);
    cudaGetSymbolAddress(&p_q,   g_q);
    cudaGetSymbolAddress(&p_k,   g_k);
    cudaGetSymbolAddress(&p_v,   g_v);
    cudaGetSymbolAddress(&p_ctx, g_ctx);
    float* xn  = (float*)p_xn;
    float* q   = (float*)p_q;
    float* k   = (float*)p_k;
    float* v   = (float*)p_v;
    float* ctx = (float*)p_ctx;

    cudaFuncSetAttribute(flash_mma_kernel,
                         cudaFuncAttributeMaxDynamicSharedMemorySize,
                         FLASH_SMEM);

    rope_table_kernel<<<SS, NF>>>();
    rmsnorm_kernel<<<NROW, 256>>>(x, rmsw);

    // projections
    sgemm64<<<dim3(HH * QD / 64, NROW / 64), 256>>>(xn, Wq, nullptr, q, NROW, HH * QD, DIM);
    sgemm64<<<dim3(1,            NROW / 64), 256>>>(xn, Wk, nullptr, k, NROW, QD, DIM);
    sgemm64<<<dim3(2,            NROW / 64), 256>>>(xn, Wv, bv,      v, NROW, VD, DIM);

    rope_q_kernel<<<NROW, 512>>>();
    rope_k_kernel<<<NROW, 32>>>();

    // attention (tensor cores)
    flash_mma_kernel<<<dim3(SS / 128, HH, BB), 256, FLASH_SMEM>>>(bias);

    // output projection
    sgemm64<<<dim3(DIM / 64, NROW / 64), 256>>>(ctx, Wo, bo, out, NROW, DIM, HV);
}

// round 7
// speedup vs baseline: 1.9290x; 1.2199x over previous
#include <cuda_runtime.h>
#include <cuda_bf16.h>
#include <math.h>
#include <stdint.h>

// Problem constants
#define BB   2
#define SS   2048
#define DIM  1024
#define HH   16
#define QD   64
#define VD   96
#define NF   32          // QD/2
#define HV   (HH*VD)     // 1536
#define NROW (BB*SS)     // 4096

// ---------------------------------------------------------------------------
// Scratch (device globals; no allocation allowed)
// ---------------------------------------------------------------------------
__device__ float g_xn [NROW*DIM];     // normalized x
__device__ float g_q  [NROW*HH*QD];   // q (post-rope), layout (b,s,h,d)
__device__ float g_k  [NROW*QD];      // k (post-rope)
__device__ float g_v  [NROW*VD];      // v
__device__ float g_ctx[NROW*HV];      // attention output, layout (b,s,h,vd)
__device__ float g_sin[SS*NF];
__device__ float g_cos[SS*NF];

// ---------------------------------------------------------------------------
// RoPE tables
// ---------------------------------------------------------------------------
__global__ void rope_table_kernel() {
    int s = blockIdx.x, i = threadIdx.x;
    double freq = exp(-((double)i / 31.0) * log(2048.0));
    double th = (double)s * freq;
    double si, co;
    sincos(th, &si, &co);
    g_sin[s*NF + i] = (float)si;
    g_cos[s*NF + i] = (float)co;
}

// ---------------------------------------------------------------------------
// RMSNorm
// ---------------------------------------------------------------------------
__global__ void rmsnorm_kernel(const float* __restrict__ x,
                               const float* __restrict__ w) {
    int row = blockIdx.x;
    int t = threadIdx.x;
    const float4* xr = (const float4*)(x + (size_t)row * DIM);
    float4 xv = xr[t];
    float ss = xv.x*xv.x + xv.y*xv.y + xv.z*xv.z + xv.w*xv.w;
    #pragma unroll
    for (int o = 16; o; o >>= 1) ss += __shfl_xor_sync(0xffffffffu, ss, o);
    __shared__ float wsum[8];
    if ((t & 31) == 0) wsum[t >> 5] = ss;
    __syncthreads();
    float tot = 0.f;
    #pragma unroll
    for (int i = 0; i < 8; i++) tot += wsum[i];
    float scale = rsqrtf(tot * (1.0f / DIM) + 1e-8f);
    const float4* wr = (const float4*)w;
    float4 wv = wr[t];
    float4 o;
    o.x = xv.x * wv.x * scale;
    o.y = xv.y * wv.y * scale;
    o.z = xv.z * wv.z * scale;
    o.w = xv.w * wv.w * scale;
    ((float4*)(g_xn + (size_t)row * DIM))[t] = o;
}

// ---------------------------------------------------------------------------
// RoPE
// ---------------------------------------------------------------------------
__global__ void rope_q_kernel() {
    int bs = blockIdx.x;
    int s = bs & (SS - 1);
    int h = threadIdx.x >> 5, i = threadIdx.x & 31;
    float* base = g_q + (size_t)bs * (HH * QD) + h * QD;
    float x1 = base[2 * i], x2 = base[2 * i + 1];
    float sn = g_sin[s * NF + i], cs = g_cos[s * NF + i];
    __syncwarp();
    base[i]      = x1 * cs - x2 * sn;
    base[32 + i] = x1 * sn + x2 * cs;
}

__global__ void rope_k_kernel() {
    int bs = blockIdx.x;
    int s = bs & (SS - 1);
    int i = threadIdx.x;
    float* base = g_k + (size_t)bs * QD;
    float x1 = base[2 * i], x2 = base[2 * i + 1];
    float sn = g_sin[s * NF + i], cs = g_cos[s * NF + i];
    __syncwarp();
    base[i]      = x1 * cs - x2 * sn;
    base[32 + i] = x1 * sn + x2 * cs;
}

// ---------------------------------------------------------------------------
// Fast math helpers (pure-FFMA, no MUFU)
// ---------------------------------------------------------------------------
__device__ __forceinline__ float fexp2(float x) {
    float y = x + 12582912.0f;
    float f = x - (y - 12582912.0f);
    int   k = __float_as_int(y) - 0x4B400000;
    float p =              1.5404e-4f;
    p = fmaf(p, f, 1.3333558e-3f);
    p = fmaf(p, f, 9.6181291e-3f);
    p = fmaf(p, f, 5.5504109e-2f);
    p = fmaf(p, f, 2.4022651e-1f);
    p = fmaf(p, f, 6.9314718e-1f);
    p = fmaf(p, f, 1.0f);
    float sc = __int_as_float((k + 127) << 23);
    return p * sc;
}

__device__ __forceinline__ float frcp(float w) {
    float r = __int_as_float(0x7EF311C3 - __float_as_int(w));
    r = r * fmaf(-w, r, 2.0f);
    r = r * fmaf(-w, r, 2.0f);
    r = r * fmaf(-w, r, 2.0f);
    return r;
}

// p = exp(5*tanh(s/5)), FMA pipe only.
__device__ __forceinline__ float softcap_exp(float s) {
    float x1 = fminf(fmaxf(s * 0.57707802f, -30.f), 30.f);
    float e2 = fexp2(x1);
    float r  = frcp(1.0f + e2);
    return fexp2(fmaf(-14.4269504f, r, 7.2134752f));
}

// ---------------------------------------------------------------------------
// MMA / ldmatrix helpers
// ---------------------------------------------------------------------------
__device__ __forceinline__ void mma_bf16(float* c, const uint32_t* a,
                                         uint32_t b0, uint32_t b1) {
    asm volatile(
        "mma.sync.aligned.m16n8k16.row.col.f32.bf16.bf16.f32 "
        "{%0,%1,%2,%3}, {%4,%5,%6,%7}, {%8,%9}, {%0,%1,%2,%3};\n"
        : "+f"(c[0]), "+f"(c[1]), "+f"(c[2]), "+f"(c[3])
        : "r"(a[0]), "r"(a[1]), "r"(a[2]), "r"(a[3]), "r"(b0), "r"(b1));
}

__device__ __forceinline__ void ldsm_x4(uint32_t* r, uint32_t addr) {
    asm volatile(
        "ldmatrix.sync.aligned.m8n8.x4.shared.b16 {%0,%1,%2,%3}, [%4];\n"
        : "=r"(r[0]), "=r"(r[1]), "=r"(r[2]), "=r"(r[3]) : "r"(addr));
}

__device__ __forceinline__ void split_store(__nv_bfloat16* hi, __nv_bfloat16* lo,
                                            int idx, float x) {
    __nv_bfloat16 h = __float2bfloat16(x);
    hi[idx] = h;
    lo[idx] = __float2bfloat16(x - __bfloat162float(h));
}

__device__ __forceinline__ uint32_t pack_hi2(float a, float b) {
    __nv_bfloat162 t;
    t.x = __float2bfloat16(a);
    t.y = __float2bfloat16(b);
    return *reinterpret_cast<uint32_t*>(&t);
}
__device__ __forceinline__ uint32_t pack_lo2(float a, float b) {
    __nv_bfloat16 ha = __float2bfloat16(a);
    __nv_bfloat16 hb = __float2bfloat16(b);
    __nv_bfloat162 t;
    t.x = __float2bfloat16(a - __bfloat162float(ha));
    t.y = __float2bfloat16(b - __bfloat162float(hb));
    return *reinterpret_cast<uint32_t*>(&t);
}

// ---------------------------------------------------------------------------
// Tensor-core flash attention (bf16 split, ldmatrix fragment loads).
// Block: 256 threads (8 warps), 128 query rows, one (b,h). j-tiles of 64.
// ---------------------------------------------------------------------------
#define QSTR 72   // smem row stride (bf16 elems); 144B stride -> LDSM conflict-free
#define FLASH_SMEM ((128 + 64 + 96) * QSTR * 2 * 2)  // 82944 bytes

__global__ __launch_bounds__(256, 1) void flash_mma_kernel(const float* __restrict__ bias) {
    extern __shared__ __nv_bfloat16 smraw[];
    __nv_bfloat16* qh = smraw;
    __nv_bfloat16* ql = qh + 128 * QSTR;
    __nv_bfloat16* kh = ql + 128 * QSTR;
    __nv_bfloat16* kl = kh + 64 * QSTR;
    __nv_bfloat16* vh = kl + 64 * QSTR;     // V transposed: [vd][j]
    __nv_bfloat16* vl = vh + 96 * QSTR;

    uint32_t qh_s = (uint32_t)__cvta_generic_to_shared(qh);
    uint32_t ql_s = (uint32_t)__cvta_generic_to_shared(ql);
    uint32_t kh_s = (uint32_t)__cvta_generic_to_shared(kh);
    uint32_t kl_s = (uint32_t)__cvta_generic_to_shared(kl);
    uint32_t vh_s = (uint32_t)__cvta_generic_to_shared(vh);
    uint32_t vl_s = (uint32_t)__cvta_generic_to_shared(vl);

    int t = threadIdx.x, w = t >> 5, l = t & 31;
    int b = blockIdx.z, h = blockIdx.y, i0 = blockIdx.x * 128;
    int gid = l >> 2, lc = l & 3;
    int m0 = w * 16;

    // load+split Q tile (128 x 64)
    for (int idx = t; idx < 128 * 64; idx += 256) {
        int r = idx >> 6, d = idx & 63;
        float x = g_q[((size_t)(b * SS + i0 + r) * HH + h) * QD + d];
        split_store(qh, ql, r * QSTR + d, x);
    }
    __syncthreads();

    // hoist Q fragments (loop-invariant): 4 k-chunks of 16
    uint32_t qah[4][4], qal[4][4];
    {
        uint32_t roff = (uint32_t)((m0 + (l & 15)) * QSTR + ((l >> 4) << 3)) * 2;
        #pragma unroll
        for (int kk = 0; kk < 4; kk++) {
            ldsm_x4(qah[kk], qh_s + roff + kk * 32);
            ldsm_x4(qal[kk], ql_s + roff + kk * 32);
        }
    }

    float o[12][4] = {};
    float lsum0 = 0.f, lsum1 = 0.f;
    const float* bb = bias + ((size_t)(b * HH + h) * SS + (i0 + m0 + gid)) * SS;

    // ldmatrix B-side address offsets: row = (l&7), col-block = (l>>3)*8
    uint32_t boff = (uint32_t)((l & 7) * QSTR + ((l >> 3) << 3)) * 2;

    for (int j0 = 0; j0 < SS; j0 += 64) {
        __syncthreads();   // previous tile's smem reads done
        for (int idx = t; idx < 64 * 64; idx += 256) {
            int r = idx >> 6, d = idx & 63;
            float x = g_k[(size_t)(b * SS + j0 + r) * QD + d];
            split_store(kh, kl, r * QSTR + d, x);
        }
        for (int idx = t; idx < 64 * 96; idx += 256) {
            int r = idx / 96, c = idx - r * 96;
            float x = g_v[(size_t)(b * SS + j0 + r) * VD + c];
            split_store(vh, vl, c * QSTR + r, x);   // transposed
        }
        __syncthreads();

        // ---- S = Q K^T + bias ----
        float sc[8][4];
        #pragma unroll
        for (int nf = 0; nf < 8; nf++) {
            const float* bp = bb + j0 + nf * 8 + lc * 2;
            float2 b01 = *(const float2*)bp;
            float2 b23 = *(const float2*)(bp + (size_t)8 * SS);
            sc[nf][0] = b01.x; sc[nf][1] = b01.y;
            sc[nf][2] = b23.x; sc[nf][3] = b23.y;
        }
        #pragma unroll
        for (int nf = 0; nf < 8; nf++) {
            uint32_t nbase = boff + (uint32_t)(nf * 8 * QSTR) * 2;
            uint32_t bh[8], bl[8];
            ldsm_x4(bh + 0, kh_s + nbase);        // k 0..31  -> kk0,kk1
            ldsm_x4(bh + 4, kh_s + nbase + 64);   // k 32..63 -> kk2,kk3
            ldsm_x4(bl + 0, kl_s + nbase);
            ldsm_x4(bl + 4, kl_s + nbase + 64);
            #pragma unroll
            for (int kk = 0; kk < 4; kk++) {
                mma_bf16(sc[nf], qah[kk], bh[2*kk], bh[2*kk+1]);
                mma_bf16(sc[nf], qah[kk], bl[2*kk], bl[2*kk+1]);
                mma_bf16(sc[nf], qal[kk], bh[2*kk], bh[2*kk+1]);
            }
        }

        // ---- softcap + exp + row sums ----
        #pragma unroll
        for (int nf = 0; nf < 8; nf++) {
            #pragma unroll
            for (int e = 0; e < 4; e++)
                sc[nf][e] = softcap_exp(sc[nf][e]);
            lsum0 += sc[nf][0] + sc[nf][1];
            lsum1 += sc[nf][2] + sc[nf][3];
        }

        // ---- repack P (C layout -> A layout, hi/lo split) ----
        uint32_t ph[4][4], pl[4][4];
        #pragma unroll
        for (int kj = 0; kj < 4; kj++) {
            ph[kj][0] = pack_hi2(sc[2*kj][0],   sc[2*kj][1]);
            ph[kj][1] = pack_hi2(sc[2*kj][2],   sc[2*kj][3]);
            ph[kj][2] = pack_hi2(sc[2*kj+1][0], sc[2*kj+1][1]);
            ph[kj][3] = pack_hi2(sc[2*kj+1][2], sc[2*kj+1][3]);
            pl[kj][0] = pack_lo2(sc[2*kj][0],   sc[2*kj][1]);
            pl[kj][1] = pack_lo2(sc[2*kj][2],   sc[2*kj][3]);
            pl[kj][2] = pack_lo2(sc[2*kj+1][0], sc[2*kj+1][1]);
            pl[kj][3] = pack_lo2(sc[2*kj+1][2], sc[2*kj+1][3]);
        }

        // ---- O += P V ----
        #pragma unroll
        for (int nf = 0; nf < 12; nf++) {
            uint32_t nbase = boff + (uint32_t)(nf * 8 * QSTR) * 2;
            uint32_t bh[8], bl[8];
            ldsm_x4(bh + 0, vh_s + nbase);        // j 0..31  -> kj0,kj1
            ldsm_x4(bh + 4, vh_s + nbase + 64);   // j 32..63 -> kj2,kj3
            ldsm_x4(bl + 0, vl_s + nbase);
            ldsm_x4(bl + 4, vl_s + nbase + 64);
            #pragma unroll
            for (int kj = 0; kj < 4; kj++) {
                mma_bf16(o[nf], ph[kj], bh[2*kj], bh[2*kj+1]);
                mma_bf16(o[nf], ph[kj], bl[2*kj], bl[2*kj+1]);
                mma_bf16(o[nf], pl[kj], bh[2*kj], bh[2*kj+1]);
            }
        }
    }

    // quad-reduce row sums
    lsum0 += __shfl_xor_sync(0xffffffffu, lsum0, 1);
    lsum0 += __shfl_xor_sync(0xffffffffu, lsum0, 2);
    lsum1 += __shfl_xor_sync(0xffffffffu, lsum1, 1);
    lsum1 += __shfl_xor_sync(0xffffffffu, lsum1, 2);
    float inv0 = frcp(lsum0), inv1 = frcp(lsum1);

    int row0 = b * SS + i0 + m0 + gid;
    #pragma unroll
    for (int nf = 0; nf < 12; nf++) {
        int vd = nf * 8 + lc * 2;
        float* p0 = g_ctx + ((size_t)row0 * HH + h) * VD + vd;
        p0[0] = o[nf][0] * inv0;
        p0[1] = o[nf][1] * inv0;
        float* p1 = p0 + (size_t)8 * HH * VD;
        p1[0] = o[nf][2] * inv1;
        p1[1] = o[nf][3] * inv1;
    }
}

// ---------------------------------------------------------------------------
// bf16-split tensor-core GEMM: C[M,N] = A[M,K] @ B[K,N] (+bias[n]).
// Block: 256 threads, tile 128(M) x 64(N), BK=32. 3-MMA split => ~2^-16 error.
// ---------------------------------------------------------------------------
#define GSTR 40   // smem k-stride (32 + 8 pad), 80B

__global__ __launch_bounds__(256) void bf16gemm(
        const float* __restrict__ A, const float* __restrict__ Bm,
        const float* __restrict__ bias, float* __restrict__ C,
        int M, int N, int K) {
    __shared__ __nv_bfloat16 ash[128 * GSTR];
    __shared__ __nv_bfloat16 asl[128 * GSTR];
    __shared__ __nv_bfloat16 bsh[64 * GSTR];
    __shared__ __nv_bfloat16 bsl[64 * GSTR];

    uint32_t ash_s = (uint32_t)__cvta_generic_to_shared(ash);
    uint32_t asl_s = (uint32_t)__cvta_generic_to_shared(asl);
    uint32_t bsh_s = (uint32_t)__cvta_generic_to_shared(bsh);
    uint32_t bsl_s = (uint32_t)__cvta_generic_to_shared(bsl);

    int t = threadIdx.x, w = t >> 5, l = t & 31;
    int gid = l >> 2, lc = l & 3;
    int m0g = blockIdx.y * 128, n0g = blockIdx.x * 64;
    int m0 = w * 16;

    float acc[8][4] = {};

    uint32_t aoff = (uint32_t)((m0 + (l & 15)) * GSTR + ((l >> 4) << 3)) * 2;
    uint32_t boff = (uint32_t)((l & 7) * GSTR + ((l >> 3) << 3)) * 2;

    for (int k0 = 0; k0 < K; k0 += 32) {
        __syncthreads();
        // A tile 128x32 (coalesced along k)
        #pragma unroll
        for (int i = 0; i < 16; i++) {
            int idx = t + i * 256;
            int r = idx >> 5, c = idx & 31;
            float x = A[(size_t)(m0g + r) * K + k0 + c];
            split_store(ash, asl, r * GSTR + c, x);
        }
        // B tile 32x64 -> transposed smem [n][k] (coalesced along n)
        #pragma unroll
        for (int i = 0; i < 8; i++) {
            int idx = t + i * 256;
            int kc = idx >> 6, nn = idx & 63;
            int n = n0g + nn;
            float x = (n < N) ? Bm[(size_t)(k0 + kc) * N + n] : 0.f;
            split_store(bsh, bsl, nn * GSTR + kc, x);
        }
        __syncthreads();

        uint32_t Ah[2][4], Al[2][4];
        #pragma unroll
        for (int kk = 0; kk < 2; kk++) {
            ldsm_x4(Ah[kk], ash_s + aoff + kk * 32);
            ldsm_x4(Al[kk], asl_s + aoff + kk * 32);
        }
        #pragma unroll
        for (int nf = 0; nf < 8; nf++) {
            uint32_t nbase = boff + (uint32_t)(nf * 8 * GSTR) * 2;
            uint32_t Bh[4], Bl[4];
            ldsm_x4(Bh, bsh_s + nbase);   // kk0,kk1
            ldsm_x4(Bl, bsl_s + nbase);
            #pragma unroll
            for (int kk = 0; kk < 2; kk++) {
                mma_bf16(acc[nf], Ah[kk], Bh[2*kk], Bh[2*kk+1]);
                mma_bf16(acc[nf], Ah[kk], Bl[2*kk], Bl[2*kk+1]);
                mma_bf16(acc[nf], Al[kk], Bh[2*kk], Bh[2*kk+1]);
            }
        }
    }

    // epilogue
    int mA = m0g + m0 + gid;
    int mB = mA + 8;
    #pragma unroll
    for (int nf = 0; nf < 8; nf++) {
        int n = n0g + nf * 8 + lc * 2;
        if (n < N) {
            float b0 = bias ? bias[n]     : 0.f;
            float b1 = bias ? bias[n + 1] : 0.f;
            C[(size_t)mA * N + n]     = acc[nf][0] + b0;
            C[(size_t)mA * N + n + 1] = acc[nf][1] + b1;
            C[(size_t)mB * N + n]     = acc[nf][2] + b0;
            C[(size_t)mB * N + n + 1] = acc[nf][3] + b1;
        }
    }
}

// ---------------------------------------------------------------------------
// Launch
// ---------------------------------------------------------------------------
extern "C" void kernel_launch(void* const* d_in, const int* in_sizes, int n_in,
                              void* d_out, int out_size) {
    const float* x    = (const float*)d_in[0];
    const float* bias = (const float*)d_in[1];
    const float* rmsw = (const float*)d_in[2];
    const float* Wq   = (const float*)d_in[3];
    const float* Wk   = (const float*)d_in[4];
    const float* Wv   = (const float*)d_in[5];
    const float* bv   = (const float*)d_in[6];
    const float* Wo   = (const float*)d_in[7];
    const float* bo   = (const float*)d_in[8];
    float* out = (float*)d_out;

    void *p_xn, *p_q, *p_k, *p_v, *p_ctx;
    cudaGetSymbolAddress(&p_xn,  g_xn);
    cudaGetSymbolAddress(&p_q,   g_q);
    cudaGetSymbolAddress(&p_k,   g_k);
    cudaGetSymbolAddress(&p_v,   g_v);
    cudaGetSymbolAddress(&p_ctx, g_ctx);
    float* xn  = (float*)p_xn;
    float* q   = (float*)p_q;
    float* k   = (float*)p_k;
    float* v   = (float*)p_v;
    float* ctx = (float*)p_ctx;

    cudaFuncSetAttribute(flash_mma_kernel,
                         cudaFuncAttributeMaxDynamicSharedMemorySize,
                         FLASH_SMEM);

    rope_table_kernel<<<SS, NF>>>();
    rmsnorm_kernel<<<NROW, 256>>>(x, rmsw);

    // projections (tensor cores, bf16 split)
    bf16gemm<<<dim3(HH * QD / 64, NROW / 128), 256>>>(xn, Wq, nullptr, q, NROW, HH * QD, DIM);
    bf16gemm<<<dim3(1,            NROW / 128), 256>>>(xn, Wk, nullptr, k, NROW, QD, DIM);
    bf16gemm<<<dim3(2,            NROW / 128), 256>>>(xn, Wv, bv,      v, NROW, VD, DIM);

    rope_q_kernel<<<NROW, 512>>>();
    rope_k_kernel<<<NROW, 32>>>();

    // attention (tensor cores)
    flash_mma_kernel<<<dim3(SS / 128, HH, BB), 256, FLASH_SMEM>>>(bias);

    // output projection
    bf16gemm<<<dim3(DIM / 64, NROW / 128), 256>>>(ctx, Wo, bo, out, NROW, DIM, HV);
}

// round 12
// speedup vs baseline: 2.4171x; 1.2530x over previous
#include <cuda_runtime.h>
#include <cuda_bf16.h>
#include <math.h>
#include <stdint.h>

// Problem constants
#define BB   2
#define SS   2048
#define DIM  1024
#define HH   16
#define QD   64
#define VD   96
#define NF   32
#define HV   (HH*VD)     // 1536
#define NROW (BB*SS)     // 4096
#define NQKV 1184        // 1024 (q) + 64 (k) + 96 (v)

// ---------------------------------------------------------------------------
// Scratch (device globals)
// ---------------------------------------------------------------------------
__device__ float g_qkv[NROW*NQKV];                       // fused qkv projection (fp32)
__device__ __nv_bfloat16 g_xnh[NROW*DIM],  g_xnl[NROW*DIM];
__device__ __nv_bfloat16 g_wqkvh[NQKV*DIM], g_wqkvl[NQKV*DIM];  // [n][k] transposed
__device__ __nv_bfloat16 g_woh[DIM*HV],    g_wol[DIM*HV];       // [n=1024][k=1536]
__device__ __nv_bfloat16 g_qh[NROW*HH*QD], g_ql[NROW*HH*QD];
__device__ __nv_bfloat16 g_kh[NROW*QD],    g_kl[NROW*QD];
__device__ __nv_bfloat16 g_vth[BB*VD*SS],  g_vtl[BB*VD*SS];     // V^T: [b][vd][s]
__device__ __nv_bfloat16 g_ctxh[NROW*HV],  g_ctxl[NROW*HV];
__device__ float g_sin[SS*NF], g_cos[SS*NF];

// ---------------------------------------------------------------------------
// helpers
// ---------------------------------------------------------------------------
__device__ __forceinline__ void split_store(__nv_bfloat16* hi, __nv_bfloat16* lo,
                                            size_t idx, float x) {
    __nv_bfloat16 h = __float2bfloat16(x);
    hi[idx] = h;
    lo[idx] = __float2bfloat16(x - __bfloat162float(h));
}

#define CP16(dst, src) \
    asm volatile("cp.async.cg.shared.global [%0], [%1], 16;\n" \
                 :: "r"(dst), "l"(src))
#define CP16P(dst, src, nbytes) \
    asm volatile("cp.async.cg.shared.global [%0], [%1], 16, %2;\n" \
                 :: "r"(dst), "l"(src), "r"(nbytes))
#define CP_COMMIT()  asm volatile("cp.async.commit_group;\n" ::: "memory")
#define CP_WAIT0()   asm volatile("cp.async.wait_group 0;\n" ::: "memory")
#define CP_WAIT1()   asm volatile("cp.async.wait_group 1;\n" ::: "memory")

__device__ __forceinline__ void mma_bf16(float* c, const uint32_t* a,
                                         uint32_t b0, uint32_t b1) {
    asm volatile(
        "mma.sync.aligned.m16n8k16.row.col.f32.bf16.bf16.f32 "
        "{%0,%1,%2,%3}, {%4,%5,%6,%7}, {%8,%9}, {%0,%1,%2,%3};\n"
        : "+f"(c[0]), "+f"(c[1]), "+f"(c[2]), "+f"(c[3])
        : "r"(a[0]), "r"(a[1]), "r"(a[2]), "r"(a[3]), "r"(b0), "r"(b1));
}

__device__ __forceinline__ void ldsm_x4(uint32_t* r, uint32_t addr) {
    asm volatile(
        "ldmatrix.sync.aligned.m8n8.x4.shared.b16 {%0,%1,%2,%3}, [%4];\n"
        : "=r"(r[0]), "=r"(r[1]), "=r"(r[2]), "=r"(r[3]) : "r"(addr));
}

__device__ __forceinline__ uint32_t pack_hi2(float a, float b) {
    __nv_bfloat162 t;
    t.x = __float2bfloat16(a);
    t.y = __float2bfloat16(b);
    return *reinterpret_cast<uint32_t*>(&t);
}
__device__ __forceinline__ uint32_t pack_lo2(float a, float b) {
    __nv_bfloat16 ha = __float2bfloat16(a);
    __nv_bfloat16 hb = __float2bfloat16(b);
    __nv_bfloat162 t;
    t.x = __float2bfloat16(a - __bfloat162float(ha));
    t.y = __float2bfloat16(b - __bfloat162float(hb));
    return *reinterpret_cast<uint32_t*>(&t);
}

// pure-FFMA exp2 / rcp (MUFU is 0.5 op/cyc/SM on B300 -> would serialize)
__device__ __forceinline__ float fexp2(float x) {
    float y = x + 12582912.0f;
    float f = x - (y - 12582912.0f);
    int   k = __float_as_int(y) - 0x4B400000;
    float p =              1.5404e-4f;
    p = fmaf(p, f, 1.3333558e-3f);
    p = fmaf(p, f, 9.6181291e-3f);
    p = fmaf(p, f, 5.5504109e-2f);
    p = fmaf(p, f, 2.4022651e-1f);
    p = fmaf(p, f, 6.9314718e-1f);
    p = fmaf(p, f, 1.0f);
    return p * __int_as_float((k + 127) << 23);
}
__device__ __forceinline__ float frcp(float w) {
    float r = __int_as_float(0x7EF311C3 - __float_as_int(w));
    r = r * fmaf(-w, r, 2.0f);
    r = r * fmaf(-w, r, 2.0f);
    r = r * fmaf(-w, r, 2.0f);
    return r;
}
__device__ __forceinline__ float softcap_exp(float s) {
    float x1 = fminf(fmaxf(s * 0.57707802f, -30.f), 30.f);
    float e2 = fexp2(x1);
    float r  = frcp(1.0f + e2);
    return fexp2(fmaf(-14.4269504f, r, 7.2134752f));
}

// ---------------------------------------------------------------------------
// RoPE tables
// ---------------------------------------------------------------------------
__global__ void rope_table_kernel() {
    int s = blockIdx.x, i = threadIdx.x;
    double freq = exp(-((double)i / 31.0) * log(2048.0));
    double th = (double)s * freq;
    double si, co;
    sincos(th, &si, &co);
    g_sin[s*NF + i] = (float)si;
    g_cos[s*NF + i] = (float)co;
}

// ---------------------------------------------------------------------------
// RMSNorm -> split bf16 xn
// ---------------------------------------------------------------------------
__global__ void rmsnorm_kernel(const float* __restrict__ x,
                               const float* __restrict__ w) {
    int row = blockIdx.x;
    int t = threadIdx.x;
    const float4* xr = (const float4*)(x + (size_t)row * DIM);
    float4 xv = xr[t];
    float ss = xv.x*xv.x + xv.y*xv.y + xv.z*xv.z + xv.w*xv.w;
    #pragma unroll
    for (int o = 16; o; o >>= 1) ss += __shfl_xor_sync(0xffffffffu, ss, o);
    __shared__ float wsum[8];
    if ((t & 31) == 0) wsum[t >> 5] = ss;
    __syncthreads();
    float tot = 0.f;
    #pragma unroll
    for (int i = 0; i < 8; i++) tot += wsum[i];
    float scale = rsqrtf(tot * (1.0f / DIM) + 1e-8f);
    const float4* wr = (const float4*)w;
    float4 wv = wr[t];
    float o4[4] = { xv.x*wv.x*scale, xv.y*wv.y*scale, xv.z*wv.z*scale, xv.w*wv.w*scale };
    size_t base = (size_t)row * DIM + t * 4;
    #pragma unroll
    for (int j = 0; j < 4; j++)
        split_store(g_xnh, g_xnl, base + j, o4[j]);
}

// ---------------------------------------------------------------------------
// Weight transpose + split: src fp32 [K][N] -> dst bf16 [noff+n][dstStride=K]
// grid (ceil(N/32), K/32), block (32,8)
// ---------------------------------------------------------------------------
__global__ void wsplit_kernel(const float* __restrict__ src,
                              __nv_bfloat16* __restrict__ dh,
                              __nv_bfloat16* __restrict__ dl,
                              int K, int N, int dstStride, int noff) {
    __shared__ float tile[32][33];
    int k0 = blockIdx.y * 32, n0 = blockIdx.x * 32;
    int tx = threadIdx.x, ty = threadIdx.y;
    #pragma unroll
    for (int i = 0; i < 4; i++) {
        int k = k0 + ty + i * 8, n = n0 + tx;
        tile[ty + i * 8][tx] = (n < N) ? src[(size_t)k * N + n] : 0.f;
    }
    __syncthreads();
    #pragma unroll
    for (int i = 0; i < 4; i++) {
        int n = n0 + ty + i * 8, k = k0 + tx;
        if (n < N)
            split_store(dh, dl, (size_t)(noff + n) * dstStride + k, tile[tx][ty + i * 8]);
    }
}

// ---------------------------------------------------------------------------
// RoPE (from fused qkv) -> split bf16
// ---------------------------------------------------------------------------
__global__ void rope_q_kernel() {
    int bs = blockIdx.x;
    int s = bs & (SS - 1);
    int h = threadIdx.x >> 5, i = threadIdx.x & 31;
    const float* base = g_qkv + (size_t)bs * NQKV + h * QD;
    float x1 = base[2 * i], x2 = base[2 * i + 1];
    float sn = g_sin[s * NF + i], cs = g_cos[s * NF + i];
    size_t di = ((size_t)bs * HH + h) * QD;
    split_store(g_qh, g_ql, di + i,      x1 * cs - x2 * sn);
    split_store(g_qh, g_ql, di + 32 + i, x1 * sn + x2 * cs);
}

__global__ void rope_k_kernel() {
    int bs = blockIdx.x;
    int s = bs & (SS - 1);
    int i = threadIdx.x;
    const float* base = g_qkv + (size_t)bs * NQKV + 1024;
    float x1 = base[2 * i], x2 = base[2 * i + 1];
    float sn = g_sin[s * NF + i], cs = g_cos[s * NF + i];
    size_t di = (size_t)bs * QD;
    split_store(g_kh, g_kl, di + i,      x1 * cs - x2 * sn);
    split_store(g_kh, g_kl, di + 32 + i, x1 * sn + x2 * cs);
}

// ---------------------------------------------------------------------------
// V: +bv, transpose to [b][vd][s], split. grid (SS/32, 3, BB), block (32,8)
// ---------------------------------------------------------------------------
__global__ void vsplit_kernel(const float* __restrict__ bv) {
    __shared__ float tile[32][33];
    int s0 = blockIdx.x * 32, vd0 = blockIdx.y * 32, b = blockIdx.z;
    int tx = threadIdx.x, ty = threadIdx.y;
    #pragma unroll
    for (int i = 0; i < 4; i++) {
        int s = s0 + ty + i * 8, vd = vd0 + tx;
        tile[ty + i * 8][tx] = g_qkv[(size_t)(b * SS + s) * NQKV + 1088 + vd] + bv[vd];
    }
    __syncthreads();
    #pragma unroll
    for (int i = 0; i < 4; i++) {
        int vd = vd0 + ty + i * 8, s = s0 + tx;
        split_store(g_vth, g_vtl, ((size_t)(b * VD + vd)) * SS + s, tile[tx][ty + i * 8]);
    }
}

// ---------------------------------------------------------------------------
// All-bf16 pipelined GEMM: C[M,N] = A @ B^T(+bias). A hi/lo [M][K] bf16,
// B hi/lo [N][K] bf16 (pre-transposed). Tile 128x64, BK=32, 2-stage cp.async.
// ---------------------------------------------------------------------------
#define GSTR 40                        // smem k-stride (elems); 80B rows
#define G_A   (128*GSTR*2)             // 10240 B (one matrix)
#define G_B   (64*GSTR*2)              // 5120 B
#define G_STAGE (2*G_A + 2*G_B)        // 30720 B
#define GEMM_SMEM (2*G_STAGE)          // 61440 B

__global__ __launch_bounds__(256) void mmagemm(
        const __nv_bfloat16* __restrict__ Ah, const __nv_bfloat16* __restrict__ Al,
        const __nv_bfloat16* __restrict__ Bh, const __nv_bfloat16* __restrict__ Bl,
        const float* __restrict__ bias, float* __restrict__ C,
        int M, int N, int K) {
    extern __shared__ char sm[];
    uint32_t smb = (uint32_t)__cvta_generic_to_shared(sm);

    int t = threadIdx.x, w = t >> 5, l = t & 31;
    int gid = l >> 2, lc = l & 3;
    int m0g = blockIdx.y * 128, n0g = blockIdx.x * 64;
    int m0 = w * 16;
    int nk = K >> 5;

    float acc[8][4] = {};

    uint32_t aoff = (uint32_t)((m0 + (l & 15)) * GSTR + ((l >> 4) << 3)) * 2;
    uint32_t boff = (uint32_t)((l & 7) * GSTR + ((l >> 3) << 3)) * 2;

    auto issue = [&](int ki, int buf) {
        uint32_t so = smb + buf * G_STAGE;
        int k0 = ki << 5;
        // A: 128 rows x 4 chunks = 512 chunks per matrix -> 2 iters
        #pragma unroll
        for (int i = 0; i < 2; i++) {
            int idx = t + i * 256;
            int r = idx >> 2, cc = idx & 3;
            size_t sOff = ((size_t)(m0g + r) * K + k0) * 2 + cc * 16;
            uint32_t d = so + r * 80 + cc * 16;
            CP16(d,        (const char*)Ah + sOff);
            CP16(d + G_A,  (const char*)Al + sOff);
        }
        // B: 64 rows x 4 chunks = 256 chunks per matrix -> 1 iter
        {
            int n = t >> 2, cc = t & 3;
            int gn = n0g + n;
            int nb = (gn < N) ? 16 : 0;
            int gnc = (gn < N) ? gn : (N - 1);
            size_t sOff = ((size_t)gnc * K + k0) * 2 + cc * 16;
            uint32_t d = so + 2 * G_A + n * 80 + cc * 16;
            CP16P(d,       (const char*)Bh + sOff, nb);
            CP16P(d + G_B, (const char*)Bl + sOff, nb);
        }
    };

    issue(0, 0);
    CP_COMMIT();

    for (int ki = 0; ki < nk; ki++) {
        if (ki + 1 < nk) {
            issue(ki + 1, (ki + 1) & 1);
            CP_COMMIT();
            CP_WAIT1();
        } else {
            CP_WAIT0();
        }
        __syncthreads();

        uint32_t sb = smb + (ki & 1) * G_STAGE;
        uint32_t ash_s = sb, asl_s = sb + G_A;
        uint32_t bsh_s = sb + 2 * G_A, bsl_s = bsh_s + G_B;

        uint32_t Ahf[2][4], Alf[2][4];
        #pragma unroll
        for (int kk = 0; kk < 2; kk++) {
            ldsm_x4(Ahf[kk], ash_s + aoff + kk * 32);
            ldsm_x4(Alf[kk], asl_s + aoff + kk * 32);
        }
        #pragma unroll
        for (int nf = 0; nf < 8; nf++) {
            uint32_t nbase = boff + (uint32_t)(nf * 8 * GSTR) * 2;
            uint32_t Bhf[4], Blf[4];
            ldsm_x4(Bhf, bsh_s + nbase);
            ldsm_x4(Blf, bsl_s + nbase);
            #pragma unroll
            for (int kk = 0; kk < 2; kk++) {
                mma_bf16(acc[nf], Ahf[kk], Bhf[2*kk], Bhf[2*kk+1]);
                mma_bf16(acc[nf], Ahf[kk], Blf[2*kk], Blf[2*kk+1]);
                mma_bf16(acc[nf], Alf[kk], Bhf[2*kk], Bhf[2*kk+1]);
            }
        }
        __syncthreads();
    }

    int mA = m0g + m0 + gid;
    int mB = mA + 8;
    #pragma unroll
    for (int nf = 0; nf < 8; nf++) {
        int n = n0g + nf * 8 + lc * 2;
        if (n < N) {
            float b0 = bias ? bias[n]     : 0.f;
            float b1 = bias ? bias[n + 1] : 0.f;
            C[(size_t)mA * N + n]     = acc[nf][0] + b0;
            C[(size_t)mA * N + n + 1] = acc[nf][1] + b1;
            C[(size_t)mB * N + n]     = acc[nf][2] + b0;
            C[(size_t)mB * N + n + 1] = acc[nf][3] + b1;
        }
    }
}

// ---------------------------------------------------------------------------
// Flash attention: all-bf16 tiles, 2-stage cp.async pipeline for K, V, bias.
// Block 256 thr, 128 q-rows, one (b,h); j-tiles of 64.
// ---------------------------------------------------------------------------
#define QSTR 72                         // row stride (elems), 144B
#define BSTR 68                         // bias row stride (floats), 272B
#define F_K  (64*QSTR*2)                // 9216
#define F_V  (96*QSTR*2)                // 13824
#define F_BI (128*BSTR*4)               // 34816
#define F_STAGE (2*F_K + 2*F_V + F_BI)  // 80896
#define F_Q  (128*QSTR*2*2)             // 36864
#define FLASH_SMEM (F_Q + 2*F_STAGE)    // 198656

__global__ __launch_bounds__(256, 1) void flash_mma_kernel(const float* __restrict__ bias) {
    extern __shared__ char sm[];
    uint32_t smb = (uint32_t)__cvta_generic_to_shared(sm);
    uint32_t qh_s = smb, ql_s = smb + 128 * QSTR * 2;

    int t = threadIdx.x, w = t >> 5, l = t & 31;
    int b = blockIdx.z, h = blockIdx.y, i0 = blockIdx.x * 128;
    int gid = l >> 2, lc = l & 3;
    int m0 = w * 16;

    auto issue_tile = [&](int jt, int buf) {
        uint32_t so = smb + F_Q + buf * F_STAGE;
        int j0 = jt << 6;
        // K hi/lo: 64 rows x 8 chunks = 512 each -> 2 iters
        #pragma unroll
        for (int i = 0; i < 2; i++) {
            int idx = t + i * 256;
            int r = idx >> 3, cc = idx & 7;
            size_t sOff = ((size_t)(b * SS + j0 + r) * QD) * 2 + cc * 16;
            uint32_t d = so + r * 144 + cc * 16;
            CP16(d,       (const char*)g_kh + sOff);
            CP16(d + F_K, (const char*)g_kl + sOff);
        }
        // V hi/lo: 96 rows x 8 chunks = 768 each -> 3 iters
        #pragma unroll
        for (int i = 0; i < 3; i++) {
            int idx = t + i * 256;
            int vd = idx >> 3, cc = idx & 7;
            size_t sOff = (((size_t)(b * VD + vd)) * SS + j0) * 2 + cc * 16;
            uint32_t d = so + 2 * F_K + vd * 144 + cc * 16;
            CP16(d,       (const char*)g_vth + sOff);
            CP16(d + F_V, (const char*)g_vtl + sOff);
        }
        // bias: 128 rows x 16 chunks = 2048 -> 8 iters
        #pragma unroll
        for (int i = 0; i < 8; i++) {
            int idx = t + i * 256;
            int m = idx >> 4, cc = idx & 15;
            size_t sOff = ((((size_t)(b * HH + h) * SS) + i0 + m) * SS + j0) * 4 + cc * 16;
            CP16(so + 2 * F_K + 2 * F_V + m * 272 + cc * 16, (const char*)bias + sOff);
        }
    };

    // prologue: Q tiles (128 rows x 8 chunks = 1024 per matrix -> 4 iters) + stage 0
    #pragma unroll
    for (int i = 0; i < 4; i++) {
        int idx = t + i * 256;
        int r = idx >> 3, cc = idx & 7;
        size_t sOff = (((size_t)(b * SS + i0 + r) * HH + h) * QD) * 2 + cc * 16;
        uint32_t d = r * 144 + cc * 16;
        CP16(qh_s + d, (const char*)g_qh + sOff);
        CP16(ql_s + d, (const char*)g_ql + sOff);
    }
    issue_tile(0, 0);
    CP_COMMIT();
    CP_WAIT0();
    __syncthreads();

    // hoist Q fragments
    uint32_t qah[4][4], qal[4][4];
    {
        uint32_t roff = (uint32_t)((m0 + (l & 15)) * QSTR + ((l >> 4) << 3)) * 2;
        #pragma unroll
        for (int kk = 0; kk < 4; kk++) {
            ldsm_x4(qah[kk], qh_s + roff + kk * 32);
            ldsm_x4(qal[kk], ql_s + roff + kk * 32);
        }
    }

    float o[12][4] = {};
    float lsum0 = 0.f, lsum1 = 0.f;
    uint32_t boff = (uint32_t)((l & 7) * QSTR + ((l >> 3) << 3)) * 2;

    for (int jt = 0; jt < SS / 64; jt++) {
        if (jt + 1 < SS / 64) {
            issue_tile(jt + 1, (jt + 1) & 1);
            CP_COMMIT();
            CP_WAIT1();
        } else {
            CP_WAIT0();
        }
        __syncthreads();

        uint32_t so = smb + F_Q + (jt & 1) * F_STAGE;
        uint32_t kh_s = so, kl_s = so + F_K;
        uint32_t vh_s = so + 2 * F_K, vl_s = vh_s + F_V;
        const float* bsm = (const float*)(sm + F_Q + (jt & 1) * F_STAGE + 2 * F_K + 2 * F_V);

        // ---- S = Q K^T + bias ----
        float scv[8][4];
        const float* br0 = bsm + (m0 + gid) * BSTR;
        const float* br1 = bsm + (m0 + gid + 8) * BSTR;
        #pragma unroll
        for (int nf = 0; nf < 8; nf++) {
            int c = nf * 8 + lc * 2;
            float2 b01 = *(const float2*)(br0 + c);
            float2 b23 = *(const float2*)(br1 + c);
            scv[nf][0] = b01.x; scv[nf][1] = b01.y;
            scv[nf][2] = b23.x; scv[nf][3] = b23.y;
        }
        #pragma unroll
        for (int nf = 0; nf < 8; nf++) {
            uint32_t nbase = boff + (uint32_t)(nf * 8 * QSTR) * 2;
            uint32_t bh[8], bl[8];
            ldsm_x4(bh + 0, kh_s + nbase);
            ldsm_x4(bh + 4, kh_s + nbase + 64);
            ldsm_x4(bl + 0, kl_s + nbase);
            ldsm_x4(bl + 4, kl_s + nbase + 64);
            #pragma unroll
            for (int kk = 0; kk < 4; kk++) {
                mma_bf16(scv[nf], qah[kk], bh[2*kk], bh[2*kk+1]);
                mma_bf16(scv[nf], qah[kk], bl[2*kk], bl[2*kk+1]);
                mma_bf16(scv[nf], qal[kk], bh[2*kk], bh[2*kk+1]);
            }
        }

        // ---- softcap + exp + row sums ----
        #pragma unroll
        for (int nf = 0; nf < 8; nf++) {
            #pragma unroll
            for (int e = 0; e < 4; e++)
                scv[nf][e] = softcap_exp(scv[nf][e]);
            lsum0 += scv[nf][0] + scv[nf][1];
            lsum1 += scv[nf][2] + scv[nf][3];
        }

        // ---- repack P to A-fragments (hi/lo) ----
        uint32_t ph[4][4], pl[4][4];
        #pragma unroll
        for (int kj = 0; kj < 4; kj++) {
            ph[kj][0] = pack_hi2(scv[2*kj][0],   scv[2*kj][1]);
            ph[kj][1] = pack_hi2(scv[2*kj][2],   scv[2*kj][3]);
            ph[kj][2] = pack_hi2(scv[2*kj+1][0], scv[2*kj+1][1]);
            ph[kj][3] = pack_hi2(scv[2*kj+1][2], scv[2*kj+1][3]);
            pl[kj][0] = pack_lo2(scv[2*kj][0],   scv[2*kj][1]);
            pl[kj][1] = pack_lo2(scv[2*kj][2],   scv[2*kj][3]);
            pl[kj][2] = pack_lo2(scv[2*kj+1][0], scv[2*kj+1][1]);
            pl[kj][3] = pack_lo2(scv[2*kj+1][2], scv[2*kj+1][3]);
        }

        // ---- O += P V ----
        #pragma unroll
        for (int nf = 0; nf < 12; nf++) {
            uint32_t nbase = boff + (uint32_t)(nf * 8 * QSTR) * 2;
            uint32_t bh[8], bl[8];
            ldsm_x4(bh + 0, vh_s + nbase);
            ldsm_x4(bh + 4, vh_s + nbase + 64);
            ldsm_x4(bl + 0, vl_s + nbase);
            ldsm_x4(bl + 4, vl_s + nbase + 64);
            #pragma unroll
            for (int kj = 0; kj < 4; kj++) {
                mma_bf16(o[nf], ph[kj], bh[2*kj], bh[2*kj+1]);
                mma_bf16(o[nf], ph[kj], bl[2*kj], bl[2*kj+1]);
                mma_bf16(o[nf], pl[kj], bh[2*kj], bh[2*kj+1]);
            }
        }
        __syncthreads();
    }

    lsum0 += __shfl_xor_sync(0xffffffffu, lsum0, 1);
    lsum0 += __shfl_xor_sync(0xffffffffu, lsum0, 2);
    lsum1 += __shfl_xor_sync(0xffffffffu, lsum1, 1);
    lsum1 += __shfl_xor_sync(0xffffffffu, lsum1, 2);
    float inv0 = frcp(lsum0), inv1 = frcp(lsum1);

    int row0 = b * SS + i0 + m0 + gid;
    #pragma unroll
    for (int nf = 0; nf < 12; nf++) {
        int vd = nf * 8 + lc * 2;
        size_t i00 = ((size_t)row0 * HH + h) * VD + vd;
        size_t i10 = i00 + (size_t)8 * HH * VD;
        split_store(g_ctxh, g_ctxl, i00,     o[nf][0] * inv0);
        split_store(g_ctxh, g_ctxl, i00 + 1, o[nf][1] * inv0);
        split_store(g_ctxh, g_ctxl, i10,     o[nf][2] * inv1);
        split_store(g_ctxh, g_ctxl, i10 + 1, o[nf][3] * inv1);
    }
}

// ---------------------------------------------------------------------------
// Launch
// ---------------------------------------------------------------------------
extern "C" void kernel_launch(void* const* d_in, const int* in_sizes, int n_in,
                              void* d_out, int out_size) {
    const float* x    = (const float*)d_in[0];
    const float* bias = (const float*)d_in[1];
    const float* rmsw = (const float*)d_in[2];
    const float* Wq   = (const float*)d_in[3];
    const float* Wk   = (const float*)d_in[4];
    const float* Wv   = (const float*)d_in[5];
    const float* bv   = (const float*)d_in[6];
    const float* Wo   = (const float*)d_in[7];
    const float* bo   = (const float*)d_in[8];
    float* out = (float*)d_out;

    void *p_xnh, *p_xnl, *p_wqh, *p_wql, *p_woh, *p_wol, *p_qkv, *p_ch, *p_cl;
    cudaGetSymbolAddress(&p_xnh, g_xnh);
    cudaGetSymbolAddress(&p_xnl, g_xnl);
    cudaGetSymbolAddress(&p_wqh, g_wqkvh);
    cudaGetSymbolAddress(&p_wql, g_wqkvl);
    cudaGetSymbolAddress(&p_woh, g_woh);
    cudaGetSymbolAddress(&p_wol, g_wol);
    cudaGetSymbolAddress(&p_qkv, g_qkv);
    cudaGetSymbolAddress(&p_ch,  g_ctxh);
    cudaGetSymbolAddress(&p_cl,  g_ctxl);

    cudaFuncSetAttribute(flash_mma_kernel,
                         cudaFuncAttributeMaxDynamicSharedMemorySize, FLASH_SMEM);
    cudaFuncSetAttribute(mmagemm,
                         cudaFuncAttributeMaxDynamicSharedMemorySize, GEMM_SMEM);

    rope_table_kernel<<<SS, NF>>>();
    rmsnorm_kernel<<<NROW, 256>>>(x, rmsw);

    // weight split+transpose
    dim3 wb(32, 8);
    wsplit_kernel<<<dim3(32, 32), wb>>>(Wq, (__nv_bfloat16*)p_wqh, (__nv_bfloat16*)p_wql, DIM, 1024, DIM, 0);
    wsplit_kernel<<<dim3(2,  32), wb>>>(Wk, (__nv_bfloat16*)p_wqh, (__nv_bfloat16*)p_wql, DIM, 64,   DIM, 1024);
    wsplit_kernel<<<dim3(3,  32), wb>>>(Wv, (__nv_bfloat16*)p_wqh, (__nv_bfloat16*)p_wql, DIM, 96,   DIM, 1088);
    wsplit_kernel<<<dim3(32, 48), wb>>>(Wo, (__nv_bfloat16*)p_woh, (__nv_bfloat16*)p_wol, HV,  1024, HV,  0);

    // fused QKV projection (fp32 out)
    mmagemm<<<dim3((NQKV + 63) / 64, NROW / 128), 256, GEMM_SMEM>>>(
        (__nv_bfloat16*)p_xnh, (__nv_bfloat16*)p_xnl,
        (__nv_bfloat16*)p_wqh, (__nv_bfloat16*)p_wql,
        nullptr, (float*)p_qkv, NROW, NQKV, DIM);

    rope_q_kernel<<<NROW, 512>>>();
    rope_k_kernel<<<NROW, 32>>>();
    vsplit_kernel<<<dim3(SS / 32, VD / 32, BB), wb>>>(bv);

    // attention
    flash_mma_kernel<<<dim3(SS / 128, HH, BB), 256, FLASH_SMEM>>>(bias);

    // output projection
    mmagemm<<<dim3(DIM / 64, NROW / 128), 256, GEMM_SMEM>>>(
        (__nv_bfloat16*)p_ch, (__nv_bfloat16*)p_cl,
        (__nv_bfloat16*)p_woh, (__nv_bfloat16*)p_wol,
        bo, out, NROW, DIM, HV);
}

// round 17
// speedup vs baseline: 3.9171x; 1.6206x over previous
#include <cuda_runtime.h>
#include <cuda_bf16.h>
#include <math.h>
#include <stdint.h>

// Problem constants
#define BB   2
#define SS   2048
#define DIM  1024
#define HH   16
#define QD   64
#define VD   96
#define NF   32
#define HV   (HH*VD)     // 1536
#define NROW (BB*SS)     // 4096
#define NQKV 1184        // 1024 (q) + 64 (k) + 96 (v)

// ---------------------------------------------------------------------------
// Scratch (device globals)
// ---------------------------------------------------------------------------
__device__ float g_qkv[NROW*NQKV];                       // fused qkv projection (fp32)
__device__ __nv_bfloat16 g_xnh[NROW*DIM],  g_xnl[NROW*DIM];
__device__ __nv_bfloat16 g_wqkvh[NQKV*DIM], g_wqkvl[NQKV*DIM];  // [n][k] transposed
__device__ __nv_bfloat16 g_woh[DIM*HV],    g_wol[DIM*HV];       // [n=1024][k=1536]
__device__ __nv_bfloat16 g_qh[NROW*HH*QD], g_ql[NROW*HH*QD];
__device__ __nv_bfloat16 g_kh[NROW*QD],    g_kl[NROW*QD];
__device__ __nv_bfloat16 g_vth[BB*VD*SS],  g_vtl[BB*VD*SS];     // V^T: [b][vd][s]
__device__ __nv_bfloat16 g_ctxh[NROW*HV],  g_ctxl[NROW*HV];
__device__ float g_sin[SS*NF], g_cos[SS*NF];

// ---------------------------------------------------------------------------
// helpers
// ---------------------------------------------------------------------------
__device__ __forceinline__ void split_store(__nv_bfloat16* hi, __nv_bfloat16* lo,
                                            size_t idx, float x) {
    __nv_bfloat16 h = __float2bfloat16(x);
    hi[idx] = h;
    lo[idx] = __float2bfloat16(x - __bfloat162float(h));
}

#define CP16(dst, src) \
    asm volatile("cp.async.cg.shared.global [%0], [%1], 16;\n" \
                 :: "r"(dst), "l"(src))
#define CP16P(dst, src, nbytes) \
    asm volatile("cp.async.cg.shared.global [%0], [%1], 16, %2;\n" \
                 :: "r"(dst), "l"(src), "r"(nbytes))
#define CP_COMMIT()  asm volatile("cp.async.commit_group;\n" ::: "memory")
#define CP_WAIT0()   asm volatile("cp.async.wait_group 0;\n" ::: "memory")
#define CP_WAIT1()   asm volatile("cp.async.wait_group 1;\n" ::: "memory")

__device__ __forceinline__ void mma_bf16(float* c, const uint32_t* a,
                                         uint32_t b0, uint32_t b1) {
    asm volatile(
        "mma.sync.aligned.m16n8k16.row.col.f32.bf16.bf16.f32 "
        "{%0,%1,%2,%3}, {%4,%5,%6,%7}, {%8,%9}, {%0,%1,%2,%3};\n"
        : "+f"(c[0]), "+f"(c[1]), "+f"(c[2]), "+f"(c[3])
        : "r"(a[0]), "r"(a[1]), "r"(a[2]), "r"(a[3]), "r"(b0), "r"(b1));
}

__device__ __forceinline__ void ldsm_x4(uint32_t* r, uint32_t addr) {
    asm volatile(
        "ldmatrix.sync.aligned.m8n8.x4.shared.b16 {%0,%1,%2,%3}, [%4];\n"
        : "=r"(r[0]), "=r"(r[1]), "=r"(r[2]), "=r"(r[3]) : "r"(addr));
}

__device__ __forceinline__ uint32_t pack_hi2(float a, float b) {
    __nv_bfloat162 t;
    t.x = __float2bfloat16(a);
    t.y = __float2bfloat16(b);
    return *reinterpret_cast<uint32_t*>(&t);
}
__device__ __forceinline__ uint32_t pack_lo2(float a, float b) {
    __nv_bfloat16 ha = __float2bfloat16(a);
    __nv_bfloat16 hb = __float2bfloat16(b);
    __nv_bfloat162 t;
    t.x = __float2bfloat16(a - __bfloat162float(ha));
    t.y = __float2bfloat16(b - __bfloat162float(hb));
    return *reinterpret_cast<uint32_t*>(&t);
}

// pure-FFMA exp2 / rcp (no MUFU)
__device__ __forceinline__ float fexp2(float x) {
    float y = x + 12582912.0f;
    float f = x - (y - 12582912.0f);
    int   k = __float_as_int(y) - 0x4B400000;
    float p =              1.5404e-4f;
    p = fmaf(p, f, 1.3333558e-3f);
    p = fmaf(p, f, 9.6181291e-3f);
    p = fmaf(p, f, 5.5504109e-2f);
    p = fmaf(p, f, 2.4022651e-1f);
    p = fmaf(p, f, 6.9314718e-1f);
    p = fmaf(p, f, 1.0f);
    return p * __int_as_float((k + 127) << 23);
}
__device__ __forceinline__ float frcp(float w) {
    float r = __int_as_float(0x7EF311C3 - __float_as_int(w));
    r = r * fmaf(-w, r, 2.0f);
    r = r * fmaf(-w, r, 2.0f);
    r = r * fmaf(-w, r, 2.0f);
    return r;
}
__device__ __forceinline__ float softcap_exp(float s) {
    float x1 = fminf(fmaxf(s * 0.57707802f, -30.f), 30.f);
    float e2 = fexp2(x1);
    float r  = frcp(1.0f + e2);
    return fexp2(fmaf(-14.4269504f, r, 7.2134752f));
}

// ---------------------------------------------------------------------------
// RoPE tables
// ---------------------------------------------------------------------------
__global__ void rope_table_kernel() {
    int s = blockIdx.x, i = threadIdx.x;
    double freq = exp(-((double)i / 31.0) * log(2048.0));
    double th = (double)s * freq;
    double si, co;
    sincos(th, &si, &co);
    g_sin[s*NF + i] = (float)si;
    g_cos[s*NF + i] = (float)co;
}

// ---------------------------------------------------------------------------
// RMSNorm -> split bf16 xn
// ---------------------------------------------------------------------------
__global__ void rmsnorm_kernel(const float* __restrict__ x,
                               const float* __restrict__ w) {
    int row = blockIdx.x;
    int t = threadIdx.x;
    const float4* xr = (const float4*)(x + (size_t)row * DIM);
    float4 xv = xr[t];
    float ss = xv.x*xv.x + xv.y*xv.y + xv.z*xv.z + xv.w*xv.w;
    #pragma unroll
    for (int o = 16; o; o >>= 1) ss += __shfl_xor_sync(0xffffffffu, ss, o);
    __shared__ float wsum[8];
    if ((t & 31) == 0) wsum[t >> 5] = ss;
    __syncthreads();
    float tot = 0.f;
    #pragma unroll
    for (int i = 0; i < 8; i++) tot += wsum[i];
    float scale = rsqrtf(tot * (1.0f / DIM) + 1e-8f);
    const float4* wr = (const float4*)w;
    float4 wv = wr[t];
    float o4[4] = { xv.x*wv.x*scale, xv.y*wv.y*scale, xv.z*wv.z*scale, xv.w*wv.w*scale };
    size_t base = (size_t)row * DIM + t * 4;
    #pragma unroll
    for (int j = 0; j < 4; j++)
        split_store(g_xnh, g_xnl, base + j, o4[j]);
}

// ---------------------------------------------------------------------------
// Weight transpose + split
// ---------------------------------------------------------------------------
__global__ void wsplit_kernel(const float* __restrict__ src,
                              __nv_bfloat16* __restrict__ dh,
                              __nv_bfloat16* __restrict__ dl,
                              int K, int N, int dstStride, int noff) {
    __shared__ float tile[32][33];
    int k0 = blockIdx.y * 32, n0 = blockIdx.x * 32;
    int tx = threadIdx.x, ty = threadIdx.y;
    #pragma unroll
    for (int i = 0; i < 4; i++) {
        int k = k0 + ty + i * 8, n = n0 + tx;
        tile[ty + i * 8][tx] = (n < N) ? src[(size_t)k * N + n] : 0.f;
    }
    __syncthreads();
    #pragma unroll
    for (int i = 0; i < 4; i++) {
        int n = n0 + ty + i * 8, k = k0 + tx;
        if (n < N)
            split_store(dh, dl, (size_t)(noff + n) * dstStride + k, tile[tx][ty + i * 8]);
    }
}

// ---------------------------------------------------------------------------
// RoPE (from fused qkv) -> split bf16
// ---------------------------------------------------------------------------
__global__ void rope_q_kernel() {
    int bs = blockIdx.x;
    int s = bs & (SS - 1);
    int h = threadIdx.x >> 5, i = threadIdx.x & 31;
    const float* base = g_qkv + (size_t)bs * NQKV + h * QD;
    float x1 = base[2 * i], x2 = base[2 * i + 1];
    float sn = g_sin[s * NF + i], cs = g_cos[s * NF + i];
    size_t di = ((size_t)bs * HH + h) * QD;
    split_store(g_qh, g_ql, di + i,      x1 * cs - x2 * sn);
    split_store(g_qh, g_ql, di + 32 + i, x1 * sn + x2 * cs);
}

__global__ void rope_k_kernel() {
    int bs = blockIdx.x;
    int s = bs & (SS - 1);
    int i = threadIdx.x;
    const float* base = g_qkv + (size_t)bs * NQKV + 1024;
    float x1 = base[2 * i], x2 = base[2 * i + 1];
    float sn = g_sin[s * NF + i], cs = g_cos[s * NF + i];
    size_t di = (size_t)bs * QD;
    split_store(g_kh, g_kl, di + i,      x1 * cs - x2 * sn);
    split_store(g_kh, g_kl, di + 32 + i, x1 * sn + x2 * cs);
}

// ---------------------------------------------------------------------------
// V: +bv, transpose to [b][vd][s], split
// ---------------------------------------------------------------------------
__global__ void vsplit_kernel(const float* __restrict__ bv) {
    __shared__ float tile[32][33];
    int s0 = blockIdx.x * 32, vd0 = blockIdx.y * 32, b = blockIdx.z;
    int tx = threadIdx.x, ty = threadIdx.y;
    #pragma unroll
    for (int i = 0; i < 4; i++) {
        int s = s0 + ty + i * 8, vd = vd0 + tx;
        tile[ty + i * 8][tx] = g_qkv[(size_t)(b * SS + s) * NQKV + 1088 + vd] + bv[vd];
    }
    __syncthreads();
    #pragma unroll
    for (int i = 0; i < 4; i++) {
        int vd = vd0 + ty + i * 8, s = s0 + tx;
        split_store(g_vth, g_vtl, ((size_t)(b * VD + vd)) * SS + s, tile[tx][ty + i * 8]);
    }
}

// ---------------------------------------------------------------------------
// All-bf16 pipelined mma.sync GEMM (unchanged from passing R12)
// ---------------------------------------------------------------------------
#define GSTR 40
#define G_A   (128*GSTR*2)
#define G_B   (64*GSTR*2)
#define G_STAGE (2*G_A + 2*G_B)
#define GEMM_SMEM (2*G_STAGE)

__global__ __launch_bounds__(256) void mmagemm(
        const __nv_bfloat16* __restrict__ Ah, const __nv_bfloat16* __restrict__ Al,
        const __nv_bfloat16* __restrict__ Bh, const __nv_bfloat16* __restrict__ Bl,
        const float* __restrict__ bias, float* __restrict__ C,
        int M, int N, int K) {
    extern __shared__ char sm[];
    uint32_t smb = (uint32_t)__cvta_generic_to_shared(sm);

    int t = threadIdx.x, w = t >> 5, l = t & 31;
    int gid = l >> 2, lc = l & 3;
    int m0g = blockIdx.y * 128, n0g = blockIdx.x * 64;
    int m0 = w * 16;
    int nk = K >> 5;

    float acc[8][4] = {};

    uint32_t aoff = (uint32_t)((m0 + (l & 15)) * GSTR + ((l >> 4) << 3)) * 2;
    uint32_t boff = (uint32_t)((l & 7) * GSTR + ((l >> 3) << 3)) * 2;

    auto issue = [&](int ki, int buf) {
        uint32_t so = smb + buf * G_STAGE;
        int k0 = ki << 5;
        #pragma unroll
        for (int i = 0; i < 2; i++) {
            int idx = t + i * 256;
            int r = idx >> 2, cc = idx & 3;
            size_t sOff = ((size_t)(m0g + r) * K + k0) * 2 + cc * 16;
            uint32_t d = so + r * 80 + cc * 16;
            CP16(d,        (const char*)Ah + sOff);
            CP16(d + G_A,  (const char*)Al + sOff);
        }
        {
            int n = t >> 2, cc = t & 3;
            int gn = n0g + n;
            int nb = (gn < N) ? 16 : 0;
            int gnc = (gn < N) ? gn : (N - 1);
            size_t sOff = ((size_t)gnc * K + k0) * 2 + cc * 16;
            uint32_t d = so + 2 * G_A + n * 80 + cc * 16;
            CP16P(d,       (const char*)Bh + sOff, nb);
            CP16P(d + G_B, (const char*)Bl + sOff, nb);
        }
    };

    issue(0, 0);
    CP_COMMIT();

    for (int ki = 0; ki < nk; ki++) {
        if (ki + 1 < nk) {
            issue(ki + 1, (ki + 1) & 1);
            CP_COMMIT();
            CP_WAIT1();
        } else {
            CP_WAIT0();
        }
        __syncthreads();

        uint32_t sb = smb + (ki & 1) * G_STAGE;
        uint32_t ash_s = sb, asl_s = sb + G_A;
        uint32_t bsh_s = sb + 2 * G_A, bsl_s = bsh_s + G_B;

        uint32_t Ahf[2][4], Alf[2][4];
        #pragma unroll
        for (int kk = 0; kk < 2; kk++) {
            ldsm_x4(Ahf[kk], ash_s + aoff + kk * 32);
            ldsm_x4(Alf[kk], asl_s + aoff + kk * 32);
        }
        #pragma unroll
        for (int nf = 0; nf < 8; nf++) {
            uint32_t nbase = boff + (uint32_t)(nf * 8 * GSTR) * 2;
            uint32_t Bhf[4], Blf[4];
            ldsm_x4(Bhf, bsh_s + nbase);
            ldsm_x4(Blf, bsl_s + nbase);
            #pragma unroll
            for (int kk = 0; kk < 2; kk++) {
                mma_bf16(acc[nf], Ahf[kk], Bhf[2*kk], Bhf[2*kk+1]);
                mma_bf16(acc[nf], Ahf[kk], Blf[2*kk], Blf[2*kk+1]);
                mma_bf16(acc[nf], Alf[kk], Bhf[2*kk], Bhf[2*kk+1]);
            }
        }
        __syncthreads();
    }

    int mA = m0g + m0 + gid;
    int mB = mA + 8;
    #pragma unroll
    for (int nf = 0; nf < 8; nf++) {
        int n = n0g + nf * 8 + lc * 2;
        if (n < N) {
            float b0 = bias ? bias[n]     : 0.f;
            float b1 = bias ? bias[n + 1] : 0.f;
            C[(size_t)mA * N + n]     = acc[nf][0] + b0;
            C[(size_t)mA * N + n + 1] = acc[nf][1] + b1;
            C[(size_t)mB * N + n]     = acc[nf][2] + b0;
            C[(size_t)mB * N + n + 1] = acc[nf][3] + b1;
        }
    }
}

// ---------------------------------------------------------------------------
// Flash attention (mma.sync): all-bf16 K/V tiles, 2-stage cp.async pipeline,
// bias via direct LDG, Q smem aliased into stage 1 -> 93KB smem, 2 CTAs/SM.
// Block 256 thr (8 warps), 128 q-rows, one (b,h); j-tiles of 64.
// ---------------------------------------------------------------------------
#define QSTR 72                          // row stride (bf16 elems), 144B
#define F_K1 (64*QSTR*2)                 // 9216 (one K matrix)
#define F_V1 (96*QSTR*2)                 // 13824 (one V matrix)
#define F_STG (2*F_K1 + 2*F_V1)          // 46080 per stage
#define F_QH  F_STG                      // Q hi aliased at stage-1 base
#define F_QL  (F_STG + 128*QSTR*2)       // +18432
#define F_LSUM (2*F_STG)                 // 92160
#define FLASH_SMEM (F_LSUM + 1056)       // 93216

__global__ __launch_bounds__(256, 2) void flash_mma_kernel(const float* __restrict__ bias) {
    extern __shared__ char sm[];
    uint32_t smb = (uint32_t)__cvta_generic_to_shared(sm);
    uint32_t qh_s = smb + F_QH, ql_s = smb + F_QL;

    int t = threadIdx.x, w = t >> 5, l = t & 31;
    int b = blockIdx.z, h = blockIdx.y, i0 = blockIdx.x * 128;
    int gid = l >> 2, lc = l & 3;
    int m0 = w * 16;

    auto issue_tile = [&](int jt, int buf) {
        uint32_t so = smb + buf * F_STG;
        int j0 = jt << 6;
        // K hi/lo: 64 rows x 8 chunks = 512 each -> 2 iters
        #pragma unroll
        for (int i = 0; i < 2; i++) {
            int idx = t + i * 256;
            int r = idx >> 3, cc = idx & 7;
            size_t sOff = ((size_t)(b * SS + j0 + r) * QD) * 2 + cc * 16;
            uint32_t d = so + r * 144 + cc * 16;
            CP16(d,        (const char*)g_kh + sOff);
            CP16(d + F_K1, (const char*)g_kl + sOff);
        }
        // V hi/lo: 96 rows x 8 chunks = 768 each -> 3 iters
        #pragma unroll
        for (int i = 0; i < 3; i++) {
            int idx = t + i * 256;
            int vd = idx >> 3, cc = idx & 7;
            size_t sOff = (((size_t)(b * VD + vd)) * SS + j0) * 2 + cc * 16;
            uint32_t d = so + 2 * F_K1 + vd * 144 + cc * 16;
            CP16(d,        (const char*)g_vth + sOff);
            CP16(d + F_V1, (const char*)g_vtl + sOff);
        }
    };

    // prologue: Q (into aliased stage-1 area) + stage 0, one group
    #pragma unroll
    for (int i = 0; i < 4; i++) {
        int idx = t + i * 256;
        int r = idx >> 3, cc = idx & 7;
        size_t sOff = (((size_t)(b * SS + i0 + r) * HH + h) * QD) * 2 + cc * 16;
        uint32_t d = r * 144 + cc * 16;
        CP16(qh_s + d, (const char*)g_qh + sOff);
        CP16(ql_s + d, (const char*)g_ql + sOff);
    }
    issue_tile(0, 0);
    CP_COMMIT();
    CP_WAIT0();
    __syncthreads();

    // hoist Q fragments (before stage 1 overwrites the Q area)
    uint32_t qah[4][4], qal[4][4];
    {
        uint32_t roff = (uint32_t)((m0 + (l & 15)) * QSTR + ((l >> 4) << 3)) * 2;
        #pragma unroll
        for (int kk = 0; kk < 4; kk++) {
            ldsm_x4(qah[kk], qh_s + roff + kk * 32);
            ldsm_x4(qal[kk], ql_s + roff + kk * 32);
        }
    }
    __syncthreads();   // all warps done reading Q before stage-1 issue

    float o[12][4] = {};
    float lsum0 = 0.f, lsum1 = 0.f;
    uint32_t boff = (uint32_t)((l & 7) * QSTR + ((l >> 3) << 3)) * 2;

    const float* br0 = bias + (((size_t)(b * HH + h) * SS) + (i0 + m0 + gid)) * SS;
    const float* br1 = br0 + (size_t)8 * SS;

    for (int jt = 0; jt < SS / 64; jt++) {
        int j0 = jt << 6;

        // bias LDGs first — latency overlaps the cp.async wait below
        float scv[8][4];
        #pragma unroll
        for (int nf = 0; nf < 8; nf++) {
            int c = j0 + nf * 8 + lc * 2;
            float2 b01 = *(const float2*)(br0 + c);
            float2 b23 = *(const float2*)(br1 + c);
            scv[nf][0] = b01.x; scv[nf][1] = b01.y;
            scv[nf][2] = b23.x; scv[nf][3] = b23.y;
        }

        if (jt + 1 < SS / 64) {
            issue_tile(jt + 1, (jt + 1) & 1);
            CP_COMMIT();
            CP_WAIT1();
        } else {
            CP_WAIT0();
        }
        __syncthreads();

        uint32_t so = smb + (jt & 1) * F_STG;
        uint32_t kh_s = so, kl_s = so + F_K1;
        uint32_t vh_s = so + 2 * F_K1, vl_s = vh_s + F_V1;

        // ---- S = Q K^T + bias ----
        #pragma unroll
        for (int nf = 0; nf < 8; nf++) {
            uint32_t nbase = boff + (uint32_t)(nf * 8 * QSTR) * 2;
            uint32_t bh[8], bl[8];
            ldsm_x4(bh + 0, kh_s + nbase);
            ldsm_x4(bh + 4, kh_s + nbase + 64);
            ldsm_x4(bl + 0, kl_s + nbase);
            ldsm_x4(bl + 4, kl_s + nbase + 64);
            #pragma unroll
            for (int kk = 0; kk < 4; kk++) {
                mma_bf16(scv[nf], qah[kk], bh[2*kk], bh[2*kk+1]);
                mma_bf16(scv[nf], qah[kk], bl[2*kk], bl[2*kk+1]);
                mma_bf16(scv[nf], qal[kk], bh[2*kk], bh[2*kk+1]);
            }
        }

        // ---- softcap + exp + row sums ----
        #pragma unroll
        for (int nf = 0; nf < 8; nf++) {
            #pragma unroll
            for (int e = 0; e < 4; e++)
                scv[nf][e] = softcap_exp(scv[nf][e]);
            lsum0 += scv[nf][0] + scv[nf][1];
            lsum1 += scv[nf][2] + scv[nf][3];
        }

        // ---- repack P to A-fragments (hi/lo) ----
        uint32_t ph[4][4], pl[4][4];
        #pragma unroll
        for (int kj = 0; kj < 4; kj++) {
            ph[kj][0] = pack_hi2(scv[2*kj][0],   scv[2*kj][1]);
            ph[kj][1] = pack_hi2(scv[2*kj][2],   scv[2*kj][3]);
            ph[kj][2] = pack_hi2(scv[2*kj+1][0], scv[2*kj+1][1]);
            ph[kj][3] = pack_hi2(scv[2*kj+1][2], scv[2*kj+1][3]);
            pl[kj][0] = pack_lo2(scv[2*kj][0],   scv[2*kj][1]);
            pl[kj][1] = pack_lo2(scv[2*kj][2],   scv[2*kj][3]);
            pl[kj][2] = pack_lo2(scv[2*kj+1][0], scv[2*kj+1][1]);
            pl[kj][3] = pack_lo2(scv[2*kj+1][2], scv[2*kj+1][3]);
        }

        // ---- O += P V ----
        #pragma unroll
        for (int nf = 0; nf < 12; nf++) {
            uint32_t nbase = boff + (uint32_t)(nf * 8 * QSTR) * 2;
            uint32_t bh[8], bl[8];
            ldsm_x4(bh + 0, vh_s + nbase);
            ldsm_x4(bh + 4, vh_s + nbase + 64);
            ldsm_x4(bl + 0, vl_s + nbase);
            ldsm_x4(bl + 4, vl_s + nbase + 64);
            #pragma unroll
            for (int kj = 0; kj < 4; kj++) {
                mma_bf16(o[nf], ph[kj], bh[2*kj], bh[2*kj+1]);
                mma_bf16(o[nf], ph[kj], bl[2*kj], bl[2*kj+1]);
                mma_bf16(o[nf], pl[kj], bh[2*kj], bh[2*kj+1]);
            }
        }
        __syncthreads();
    }

    lsum0 += __shfl_xor_sync(0xffffffffu, lsum0, 1);
    lsum0 += __shfl_xor_sync(0xffffffffu, lsum0, 2);
    lsum1 += __shfl_xor_sync(0xffffffffu, lsum1, 1);
    lsum1 += __shfl_xor_sync(0xffffffffu, lsum1, 2);
    float inv0 = frcp(lsum0), inv1 = frcp(lsum1);

    int row0 = b * SS + i0 + m0 + gid;
    #pragma unroll
    for (int nf = 0; nf < 12; nf++) {
        int vd = nf * 8 + lc * 2;
        size_t i00 = ((size_t)row0 * HH + h) * VD + vd;
        size_t i10 = i00 + (size_t)8 * HH * VD;
        split_store(g_ctxh, g_ctxl, i00,     o[nf][0] * inv0);
        split_store(g_ctxh, g_ctxl, i00 + 1, o[nf][1] * inv0);
        split_store(g_ctxh, g_ctxl, i10,     o[nf][2] * inv1);
        split_store(g_ctxh, g_ctxl, i10 + 1, o[nf][3] * inv1);
    }
}

// ---------------------------------------------------------------------------
// Launch
// ---------------------------------------------------------------------------
extern "C" void kernel_launch(void* const* d_in, const int* in_sizes, int n_in,
                              void* d_out, int out_size) {
    const float* x    = (const float*)d_in[0];
    const float* bias = (const float*)d_in[1];
    const float* rmsw = (const float*)d_in[2];
    const float* Wq   = (const float*)d_in[3];
    const float* Wk   = (const float*)d_in[4];
    const float* Wv   = (const float*)d_in[5];
    const float* bv   = (const float*)d_in[6];
    const float* Wo   = (const float*)d_in[7];
    const float* bo   = (const float*)d_in[8];
    float* out = (float*)d_out;

    void *p_xnh, *p_xnl, *p_wqh, *p_wql, *p_woh, *p_wol, *p_qkv, *p_ch, *p_cl;
    cudaGetSymbolAddress(&p_xnh, g_xnh);
    cudaGetSymbolAddress(&p_xnl, g_xnl);
    cudaGetSymbolAddress(&p_wqh, g_wqkvh);
    cudaGetSymbolAddress(&p_wql, g_wqkvl);
    cudaGetSymbolAddress(&p_woh, g_woh);
    cudaGetSymbolAddress(&p_wol, g_wol);
    cudaGetSymbolAddress(&p_qkv, g_qkv);
    cudaGetSymbolAddress(&p_ch,  g_ctxh);
    cudaGetSymbolAddress(&p_cl,  g_ctxl);

    cudaFuncSetAttribute(flash_mma_kernel,
                         cudaFuncAttributeMaxDynamicSharedMemorySize, FLASH_SMEM);
    cudaFuncSetAttribute(mmagemm,
                         cudaFuncAttributeMaxDynamicSharedMemorySize, GEMM_SMEM);

    rope_table_kernel<<<SS, NF>>>();
    rmsnorm_kernel<<<NROW, 256>>>(x, rmsw);

    dim3 wb(32, 8);
    wsplit_kernel<<<dim3(32, 32), wb>>>(Wq, (__nv_bfloat16*)p_wqh, (__nv_bfloat16*)p_wql, DIM, 1024, DIM, 0);
    wsplit_kernel<<<dim3(2,  32), wb>>>(Wk, (__nv_bfloat16*)p_wqh, (__nv_bfloat16*)p_wql, DIM, 64,   DIM, 1024);
    wsplit_kernel<<<dim3(3,  32), wb>>>(Wv, (__nv_bfloat16*)p_wqh, (__nv_bfloat16*)p_wql, DIM, 96,   DIM, 1088);
    wsplit_kernel<<<dim3(32, 48), wb>>>(Wo, (__nv_bfloat16*)p_woh, (__nv_bfloat16*)p_wol, HV,  1024, HV,  0);

    mmagemm<<<dim3((NQKV + 63) / 64, NROW / 128), 256, GEMM_SMEM>>>(
        (__nv_bfloat16*)p_xnh, (__nv_bfloat16*)p_xnl,
        (__nv_bfloat16*)p_wqh, (__nv_bfloat16*)p_wql,
        nullptr, (float*)p_qkv, NROW, NQKV, DIM);

    rope_q_kernel<<<NROW, 512>>>();
    rope_k_kernel<<<NROW, 32>>>();
    vsplit_kernel<<<dim3(SS / 32, VD / 32, BB), wb>>>(bv);

    flash_mma_kernel<<<dim3(SS / 128, HH, BB), 256, FLASH_SMEM>>>(bias);

    mmagemm<<<dim3(DIM / 64, NROW / 128), 256, GEMM_SMEM>>>(
        (__nv_bfloat16*)p_ch, (__nv_bfloat16*)p_cl,
        (__nv_bfloat16*)p_woh, (__nv_bfloat16*)p_wol,
        bo, out, NROW, DIM, HV);
}